// round 6
// baseline (speedup 1.0000x reference)
#include <cuda_runtime.h>
#include <cuda_bf16.h>
#include <math.h>
#include <stdint.h>

// Problem constants
#define BATCH   4
#define SEQ     2048
#define DMODEL  1024
#define NHEAD   16
#define DH      64
#define MTOT    (BATCH * SEQ)       // 8192
#define QKV_N   (3 * DMODEL)        // 3072
#define KDIM    DMODEL

// ---------------------------------------------------------------------------
// Scratch (device globals: allocation-free rule)
// ---------------------------------------------------------------------------
__device__ float g_qkv[(size_t)MTOT * QKV_N];      // [8192,3072] tf32-rounded
__device__ float g_att[(size_t)MTOT * DMODEL];     // [8192,1024] tf32-rounded
__device__ float g_xr[(size_t)MTOT * DMODEL];      // x rounded to tf32
__device__ float g_wt_qkv[(size_t)QKV_N * DMODEL]; // W_qkv^T rounded
__device__ float g_wt_out[(size_t)DMODEL * DMODEL];// W_out^T rounded

// ---------------------------------------------------------------------------
// Helpers (portable sm_80+ PTX only)
// ---------------------------------------------------------------------------
__device__ __forceinline__ uint32_t smem_u32(const void* p) {
    uint32_t a;
    asm("{ .reg .u64 t; cvta.to.shared.u64 t, %1; cvt.u32.u64 %0, t; }" : "=r"(a) : "l"(p));
    return a;
}
__device__ __forceinline__ float round_tf32(float x) {
    uint32_t u;
    asm("cvt.rna.tf32.f32 %0, %1;" : "=r"(u) : "f"(x));
    return __uint_as_float(u);
}
__device__ __forceinline__ void cp16(uint32_t dst, const void* src) {
    asm volatile("cp.async.cg.shared.global [%0], [%1], 16;" :: "r"(dst), "l"(src));
}
#define CP_COMMIT()  asm volatile("cp.async.commit_group;" ::: "memory")
#define CP_WAIT1()   asm volatile("cp.async.wait_group 1;" ::: "memory")
#define CP_WAIT0()   asm volatile("cp.async.wait_group 0;" ::: "memory")

__device__ __forceinline__ void mma_tf32(float* d, const uint32_t* a, const uint32_t* b) {
    asm volatile(
        "mma.sync.aligned.m16n8k8.row.col.f32.tf32.tf32.f32 "
        "{%0,%1,%2,%3}, {%4,%5,%6,%7}, {%8,%9}, {%0,%1,%2,%3};"
        : "+f"(d[0]), "+f"(d[1]), "+f"(d[2]), "+f"(d[3])
        : "r"(a[0]), "r"(a[1]), "r"(a[2]), "r"(a[3]), "r"(b[0]), "r"(b[1]));
}

// ---------------------------------------------------------------------------
// Wide tf32 GEMM (unchanged from round 5): C = A @ Bt^T + bias
// CTA tile 128x256, BK=32, 8 warps, warp tile 64x64, 3-stage cp.async.
// ---------------------------------------------------------------------------
#define WBM 128
#define WBN 256
#define WBK 32
#define WP  36
#define WA_FLOATS (WBM * WP)
#define WB_FLOATS (WBN * WP)
#define WSTAGE    (WA_FLOATS + WB_FLOATS)
#define WSMEM_BYTES (3 * WSTAGE * 4)
#define NCHUNK (KDIM / WBK)

template <int DO_ROUND>
__global__ __launch_bounds__(256, 1)
void gemm_tf32_wide(const float* __restrict__ A, const float* __restrict__ Bt,
                    const float* __restrict__ bias, float* __restrict__ C, int Ntot)
{
    extern __shared__ float sm[];

    const int tid = threadIdx.x;
    const int wid = tid >> 5;
    const int lane = tid & 31;
    const int g = lane >> 2;
    const int t = lane & 3;
    const int wm = wid >> 2;
    const int wn = wid & 3;

    const int m0 = blockIdx.y * WBM;
    const int n0 = blockIdx.x * WBN;

    const float* Abase = A  + (size_t)m0 * KDIM;
    const float* Bbase = Bt + (size_t)n0 * KDIM;
    const uint32_t smu = smem_u32(sm);

    auto load_chunk = [&](int c, int st) {
        const int k0 = c * WBK;
        const uint32_t sa = smu + (uint32_t)(st * WSTAGE) * 4u;
        const uint32_t sb = sa + (uint32_t)WA_FLOATS * 4u;
#pragma unroll
        for (int i = 0; i < 4; ++i) {
            const int e = tid + 256 * i;
            const int r = e >> 3, q = e & 7;
            cp16(sa + (uint32_t)(r * WP + q * 4) * 4u, Abase + (size_t)r * KDIM + k0 + q * 4);
        }
#pragma unroll
        for (int i = 0; i < 8; ++i) {
            const int e = tid + 256 * i;
            const int r = e >> 3, q = e & 7;
            cp16(sb + (uint32_t)(r * WP + q * 4) * 4u, Bbase + (size_t)r * KDIM + k0 + q * 4);
        }
        CP_COMMIT();
    };

    float acc[4][8][4];
#pragma unroll
    for (int i = 0; i < 4; ++i)
#pragma unroll
        for (int j = 0; j < 8; ++j)
#pragma unroll
            for (int r = 0; r < 4; ++r) acc[i][j][r] = 0.f;

    load_chunk(0, 0);
    load_chunk(1, 1);

    for (int c = 0; c < NCHUNK; ++c) {
        const int s = c % 3;
        if (c + 1 < NCHUNK) CP_WAIT1(); else CP_WAIT0();
        __syncthreads();

        const float* As = sm + s * WSTAGE;
        const float* Bs = As + WA_FLOATS;

#pragma unroll
        for (int ks = 0; ks < 4; ++ks) {
            const int koff = ks * 8;
            uint32_t af[4][4];
#pragma unroll
            for (int mt = 0; mt < 4; ++mt) {
                const int rb = wm * 64 + mt * 16;
                af[mt][0] = __float_as_uint(As[(rb + g)     * WP + koff + t]);
                af[mt][1] = __float_as_uint(As[(rb + g + 8) * WP + koff + t]);
                af[mt][2] = __float_as_uint(As[(rb + g)     * WP + koff + t + 4]);
                af[mt][3] = __float_as_uint(As[(rb + g + 8) * WP + koff + t + 4]);
            }
#pragma unroll
            for (int nt = 0; nt < 8; ++nt) {
                const int nb = wn * 64 + nt * 8;
                uint32_t bf[2];
                bf[0] = __float_as_uint(Bs[(nb + g) * WP + koff + t]);
                bf[1] = __float_as_uint(Bs[(nb + g) * WP + koff + t + 4]);
#pragma unroll
                for (int mt = 0; mt < 4; ++mt)
                    mma_tf32(acc[mt][nt], af[mt], bf);
            }
        }

        if (c + 2 < NCHUNK) load_chunk(c + 2, (c + 2) % 3);
    }

#pragma unroll
    for (int mt = 0; mt < 4; ++mt) {
        const int row = m0 + wm * 64 + mt * 16 + g;
#pragma unroll
        for (int nt = 0; nt < 8; ++nt) {
            const int col = n0 + wn * 64 + nt * 8 + t * 2;
            const float bx = __ldg(bias + col), by = __ldg(bias + col + 1);
            float2 lo, hi;
            if (DO_ROUND) {
                lo = { round_tf32(acc[mt][nt][0] + bx), round_tf32(acc[mt][nt][1] + by) };
                hi = { round_tf32(acc[mt][nt][2] + bx), round_tf32(acc[mt][nt][3] + by) };
            } else {
                lo = { acc[mt][nt][0] + bx, acc[mt][nt][1] + by };
                hi = { acc[mt][nt][2] + bx, acc[mt][nt][3] + by };
            }
            *(float2*)(C + (size_t)row * Ntot + col)       = lo;
            *(float2*)(C + (size_t)(row + 8) * Ntot + col) = hi;
        }
    }
}

// ---------------------------------------------------------------------------
// Preconditioning kernels
// ---------------------------------------------------------------------------
__global__ __launch_bounds__(256)
void transpose_round_kernel(const float* __restrict__ W, float* __restrict__ Wt, int N)
{
    __shared__ float tbuf[32][33];
    const int nb = blockIdx.x * 32, kb = blockIdx.y * 32;
    const int tx = threadIdx.x, ty = threadIdx.y;
#pragma unroll
    for (int i = 0; i < 32; i += 8)
        tbuf[ty + i][tx] = W[(size_t)(kb + ty + i) * N + nb + tx];
    __syncthreads();
#pragma unroll
    for (int i = 0; i < 32; i += 8)
        Wt[(size_t)(nb + ty + i) * KDIM + kb + tx] = round_tf32(tbuf[tx][ty + i]);
}

__global__ __launch_bounds__(256)
void round_x_kernel(const float* __restrict__ x, float* __restrict__ xr, int n4)
{
    int i = blockIdx.x * blockDim.x + threadIdx.x;
    if (i < n4) {
        float4 v = ((const float4*)x)[i];
        v.x = round_tf32(v.x); v.y = round_tf32(v.y);
        v.z = round_tf32(v.z); v.w = round_tf32(v.w);
        ((float4*)xr)[i] = v;
    }
}

// ---------------------------------------------------------------------------
// Tensor-core causal flash attention, tf32 mma.sync.
// CTA: one (b,h) x 128 q rows, 8 warps x 16 rows (warp-local softmax).
// 32-key tiles, DOUBLE-BUFFERED K/V (cp.async overlaps compute), 2 CTAs/SM.
// Pitches: Q/K 68, V 72, P 36 — all fragment LDS bank-conflict-free.
// ---------------------------------------------------------------------------
#define AQP 68
#define AKP 68
#define AVP 72
#define APP 36
#define OFF_Q   0
#define OFF_K0  8704            // 128*68
#define OFF_K1  10880           // +32*68
#define OFF_V0  13056           // +32*68
#define OFF_V1  15360           // +32*72
#define OFF_P   17664           // +32*72
#define ATT_SMEM_FLOATS 22272   // +128*36
#define ATT_SMEM_BYTES  (ATT_SMEM_FLOATS * 4)

__global__ __launch_bounds__(256)
void attn_mma_kernel(const float* __restrict__ qkv, float* __restrict__ out)
{
    extern __shared__ float sm[];
    const uint32_t smu = smem_u32(sm);

    const int tid = threadIdx.x;
    const int wid = tid >> 5;
    const int lane = tid & 31;
    const int g = lane >> 2, t = lane & 3;

    const int qt = gridDim.x - 1 - blockIdx.x;   // heavy tiles first
    const int q0 = qt * 128;
    const int bh = blockIdx.y;
    const int b = bh >> 4, h = bh & 15;

    const float* base = qkv + (size_t)b * SEQ * QKV_N;

    // K/V tile loader: 32 rows x 64 floats each = 512+512 16B segs, 4/thread
    auto load_kv = [&](int kt, int st) {
        const int k0 = kt * 32;
        const uint32_t kb = smu + (uint32_t)(st ? OFF_K1 : OFF_K0) * 4u;
        const uint32_t vb = smu + (uint32_t)(st ? OFF_V1 : OFF_V0) * 4u;
#pragma unroll
        for (int i = 0; i < 2; ++i) {
            const int e = tid + 256 * i;       // 0..511
            const int r = e >> 4, seg = e & 15;
            const float* krow = base + (size_t)(k0 + r) * QKV_N + DMODEL + h * DH + seg * 4;
            const float* vrow = base + (size_t)(k0 + r) * QKV_N + 2 * DMODEL + h * DH + seg * 4;
            cp16(kb + (uint32_t)(r * AKP + seg * 4) * 4u, krow);
            cp16(vb + (uint32_t)(r * AVP + seg * 4) * 4u, vrow);
        }
        CP_COMMIT();
    };

    // stage Q (part of group 0, together with first K/V tile)
#pragma unroll
    for (int i = 0; i < 8; ++i) {
        const int e = tid + 256 * i;           // 0..2047
        const int r = e >> 4, seg = e & 15;
        cp16(smu + (uint32_t)(r * AQP + seg * 4) * 4u,
             base + (size_t)(q0 + r) * QKV_N + h * DH + seg * 4);
    }
    const int niter = 4 * (qt + 1);
    load_kv(0, 0);                              // G0 = Q + KV0
    if (niter > 1) load_kv(1, 1);               // G1 = KV1

    const int row0 = wid * 16 + g;
    const int qrow0 = q0 + row0;
    const int qrow1 = qrow0 + 8;
    const float scale = 0.125f;

    float m0 = -INFINITY, m1 = -INFINITY, l0 = 0.f, l1 = 0.f;
    float accO[8][4];
#pragma unroll
    for (int nt = 0; nt < 8; ++nt)
#pragma unroll
        for (int r = 0; r < 4; ++r) accO[nt][r] = 0.f;

    for (int it = 0; it < niter; ++it) {
        const int s = it & 1;
        const int k0 = it * 32;
        if (it + 1 < niter) CP_WAIT1(); else CP_WAIT0();
        __syncthreads();                        // tile `it` visible to all warps

        const float* Ks = sm + (s ? OFF_K1 : OFF_K0);
        const float* Vs = sm + (s ? OFF_V1 : OFF_V0);

        // ---- S = Q K^T  (16 x 32 per warp) ----
        float accS[4][4];
#pragma unroll
        for (int nt = 0; nt < 4; ++nt)
#pragma unroll
            for (int r = 0; r < 4; ++r) accS[nt][r] = 0.f;

#pragma unroll
        for (int kd = 0; kd < 8; ++kd) {
            const int koff = kd * 8;
            uint32_t a[4];
            a[0] = __float_as_uint(sm[(row0)     * AQP + koff + t]);
            a[1] = __float_as_uint(sm[(row0 + 8) * AQP + koff + t]);
            a[2] = __float_as_uint(sm[(row0)     * AQP + koff + t + 4]);
            a[3] = __float_as_uint(sm[(row0 + 8) * AQP + koff + t + 4]);
#pragma unroll
            for (int nt = 0; nt < 4; ++nt) {
                uint32_t bf[2];
                bf[0] = __float_as_uint(Ks[(nt * 8 + g) * AKP + koff + t]);
                bf[1] = __float_as_uint(Ks[(nt * 8 + g) * AKP + koff + t + 4]);
                mma_tf32(accS[nt], a, bf);
            }
        }

        // ---- scale + causal mask + online softmax ----
        float pm0 = -INFINITY, pm1 = -INFINITY;
#pragma unroll
        for (int nt = 0; nt < 4; ++nt) {
            const int key = k0 + nt * 8 + 2 * t;
            accS[nt][0] = (key     <= qrow0) ? accS[nt][0] * scale : -INFINITY;
            accS[nt][1] = (key + 1 <= qrow0) ? accS[nt][1] * scale : -INFINITY;
            accS[nt][2] = (key     <= qrow1) ? accS[nt][2] * scale : -INFINITY;
            accS[nt][3] = (key + 1 <= qrow1) ? accS[nt][3] * scale : -INFINITY;
            pm0 = fmaxf(pm0, fmaxf(accS[nt][0], accS[nt][1]));
            pm1 = fmaxf(pm1, fmaxf(accS[nt][2], accS[nt][3]));
        }
        pm0 = fmaxf(pm0, __shfl_xor_sync(0xffffffffu, pm0, 1));
        pm0 = fmaxf(pm0, __shfl_xor_sync(0xffffffffu, pm0, 2));
        pm1 = fmaxf(pm1, __shfl_xor_sync(0xffffffffu, pm1, 1));
        pm1 = fmaxf(pm1, __shfl_xor_sync(0xffffffffu, pm1, 2));

        const float mn0 = fmaxf(m0, pm0), mn1 = fmaxf(m1, pm1);
        const float c0 = __expf(m0 - mn0), c1 = __expf(m1 - mn1);
        float ls0 = 0.f, ls1 = 0.f;
#pragma unroll
        for (int nt = 0; nt < 4; ++nt) {
            const float p0 = __expf(accS[nt][0] - mn0);
            const float p1 = __expf(accS[nt][1] - mn0);
            const float p2 = __expf(accS[nt][2] - mn1);
            const float p3 = __expf(accS[nt][3] - mn1);
            ls0 += p0 + p1; ls1 += p2 + p3;
            float2 lo = { round_tf32(p0), round_tf32(p1) };
            float2 hi = { round_tf32(p2), round_tf32(p3) };
            *(float2*)&sm[OFF_P + (row0)     * APP + nt * 8 + 2 * t] = lo;
            *(float2*)&sm[OFF_P + (row0 + 8) * APP + nt * 8 + 2 * t] = hi;
        }
        ls0 += __shfl_xor_sync(0xffffffffu, ls0, 1);
        ls0 += __shfl_xor_sync(0xffffffffu, ls0, 2);
        ls1 += __shfl_xor_sync(0xffffffffu, ls1, 1);
        ls1 += __shfl_xor_sync(0xffffffffu, ls1, 2);
        l0 = l0 * c0 + ls0;
        l1 = l1 * c1 + ls1;
        m0 = mn0; m1 = mn1;
#pragma unroll
        for (int nt = 0; nt < 8; ++nt) {
            accO[nt][0] *= c0; accO[nt][1] *= c0;
            accO[nt][2] *= c1; accO[nt][3] *= c1;
        }
        __syncwarp();   // P tile is warp-private

        // ---- O += P V  (16 x 64 per warp, k = 32 keys) ----
#pragma unroll
        for (int kc = 0; kc < 4; ++kc) {
            uint32_t a[4];
            a[0] = __float_as_uint(sm[OFF_P + (row0)     * APP + kc * 8 + t]);
            a[1] = __float_as_uint(sm[OFF_P + (row0 + 8) * APP + kc * 8 + t]);
            a[2] = __float_as_uint(sm[OFF_P + (row0)     * APP + kc * 8 + t + 4]);
            a[3] = __float_as_uint(sm[OFF_P + (row0 + 8) * APP + kc * 8 + t + 4]);
#pragma unroll
            for (int nt = 0; nt < 8; ++nt) {
                uint32_t bf[2];
                bf[0] = __float_as_uint(Vs[(kc * 8 + t)     * AVP + nt * 8 + g]);
                bf[1] = __float_as_uint(Vs[(kc * 8 + t + 4) * AVP + nt * 8 + g]);
                mma_tf32(accO[nt], a, bf);
            }
        }

        __syncthreads();                        // all warps done with buffer s
        if (it + 2 < niter) load_kv(it + 2, s); // prefetch into freed buffer
    }

    // ---- normalize + write (tf32-rounded: feeds tf32 out-proj) ----
    const float rl0 = 1.0f / l0, rl1 = 1.0f / l1;
    float* o0 = out + (size_t)(b * SEQ + qrow0) * DMODEL + h * DH;
    float* o1 = out + (size_t)(b * SEQ + qrow1) * DMODEL + h * DH;
#pragma unroll
    for (int nt = 0; nt < 8; ++nt) {
        const int col = nt * 8 + 2 * t;
        float2 lo = { round_tf32(accO[nt][0] * rl0), round_tf32(accO[nt][1] * rl0) };
        float2 hi = { round_tf32(accO[nt][2] * rl1), round_tf32(accO[nt][3] * rl1) };
        *(float2*)(o0 + col) = lo;
        *(float2*)(o1 + col) = hi;
    }
}

// ---------------------------------------------------------------------------
// kernel_launch
// ---------------------------------------------------------------------------
extern "C" void kernel_launch(void* const* d_in, const int* in_sizes, int n_in,
                              void* d_out, int out_size)
{
    const float* x     = (const float*)d_in[0];
    const float* W_qkv = (const float*)d_in[1];
    const float* b_qkv = (const float*)d_in[2];
    const float* W_out = (const float*)d_in[3];
    const float* b_out = (const float*)d_in[4];
    float* out = (float*)d_out;

    float* qkv;  cudaGetSymbolAddress((void**)&qkv,  g_qkv);
    float* att;  cudaGetSymbolAddress((void**)&att,  g_att);
    float* xr;   cudaGetSymbolAddress((void**)&xr,   g_xr);
    float* wtq;  cudaGetSymbolAddress((void**)&wtq,  g_wt_qkv);
    float* wto;  cudaGetSymbolAddress((void**)&wto,  g_wt_out);

    cudaFuncSetAttribute(gemm_tf32_wide<1>,
                         cudaFuncAttributeMaxDynamicSharedMemorySize, WSMEM_BYTES);
    cudaFuncSetAttribute(gemm_tf32_wide<0>,
                         cudaFuncAttributeMaxDynamicSharedMemorySize, WSMEM_BYTES);
    cudaFuncSetAttribute(attn_mma_kernel,
                         cudaFuncAttributeMaxDynamicSharedMemorySize, ATT_SMEM_BYTES);

    // 0) precondition inputs to tf32
    {
        int n4 = MTOT * DMODEL / 4;
        round_x_kernel<<<(n4 + 255) / 256, 256>>>(x, xr, n4);
        transpose_round_kernel<<<dim3(QKV_N / 32, KDIM / 32), dim3(32, 8)>>>(W_qkv, wtq, QKV_N);
        transpose_round_kernel<<<dim3(DMODEL / 32, KDIM / 32), dim3(32, 8)>>>(W_out, wto, DMODEL);
    }
    // 1) QKV projection, output rounded to tf32
    {
        dim3 grid(QKV_N / WBN, MTOT / WBM);   // (12, 64)
        gemm_tf32_wide<1><<<grid, 256, WSMEM_BYTES>>>(xr, wtq, b_qkv, qkv, QKV_N);
    }
    // 2) Causal attention (tf32 mma.sync, double-buffered K/V)
    {
        dim3 grid(SEQ / 128, BATCH * NHEAD);  // (16, 64)
        attn_mma_kernel<<<grid, 256, ATT_SMEM_BYTES>>>(qkv, att);
    }
    // 3) Output projection, full fp32 output
    {
        dim3 grid(DMODEL / WBN, MTOT / WBM);  // (4, 64)
        gemm_tf32_wide<0><<<grid, 256, WSMEM_BYTES>>>(att, wto, b_out, out, DMODEL);
    }
}

// round 7
// speedup vs baseline: 1.0117x; 1.0117x over previous
#include <cuda_runtime.h>
#include <cuda_bf16.h>
#include <math.h>
#include <stdint.h>

// Problem constants
#define BATCH   4
#define SEQ     2048
#define DMODEL  1024
#define NHEAD   16
#define DH      64
#define MTOT    (BATCH * SEQ)       // 8192
#define QKV_N   (3 * DMODEL)        // 3072
#define KDIM    DMODEL

// ---------------------------------------------------------------------------
// Scratch (device globals: allocation-free rule)
// ---------------------------------------------------------------------------
__device__ float g_qkv[(size_t)MTOT * QKV_N];      // [8192,3072] tf32-rounded
__device__ float g_att[(size_t)MTOT * DMODEL];     // [8192,1024] tf32-rounded
__device__ float g_xr[(size_t)MTOT * DMODEL];      // x rounded to tf32
__device__ float g_wt_qkv[(size_t)QKV_N * DMODEL]; // W_qkv^T rounded
__device__ float g_wt_out[(size_t)DMODEL * DMODEL];// W_out^T rounded

// ---------------------------------------------------------------------------
// Helpers (portable sm_80+ PTX only)
// ---------------------------------------------------------------------------
__device__ __forceinline__ uint32_t smem_u32(const void* p) {
    uint32_t a;
    asm("{ .reg .u64 t; cvta.to.shared.u64 t, %1; cvt.u32.u64 %0, t; }" : "=r"(a) : "l"(p));
    return a;
}
__device__ __forceinline__ float round_tf32(float x) {
    uint32_t u;
    asm("cvt.rna.tf32.f32 %0, %1;" : "=r"(u) : "f"(x));
    return __uint_as_float(u);
}
__device__ __forceinline__ void cp16(uint32_t dst, const void* src) {
    asm volatile("cp.async.cg.shared.global [%0], [%1], 16;" :: "r"(dst), "l"(src));
}
#define CP_COMMIT()  asm volatile("cp.async.commit_group;" ::: "memory")
#define CP_WAIT1()   asm volatile("cp.async.wait_group 1;" ::: "memory")
#define CP_WAIT0()   asm volatile("cp.async.wait_group 0;" ::: "memory")

__device__ __forceinline__ void mma_tf32(float* d, const uint32_t* a, const uint32_t* b) {
    asm volatile(
        "mma.sync.aligned.m16n8k8.row.col.f32.tf32.tf32.f32 "
        "{%0,%1,%2,%3}, {%4,%5,%6,%7}, {%8,%9}, {%0,%1,%2,%3};"
        : "+f"(d[0]), "+f"(d[1]), "+f"(d[2]), "+f"(d[3])
        : "r"(a[0]), "r"(a[1]), "r"(a[2]), "r"(a[3]), "r"(b[0]), "r"(b[1]));
}

// ---------------------------------------------------------------------------
// GEMM1: 384-thread CTA (12 warps, 2x6), tile 128x384, warp 64x64, BK=32,
// 3-stage cp.async. C = A @ Bt^T + bias, output tf32-rounded.
// ---------------------------------------------------------------------------
#define P36 36
#define G1_M 128
#define G1_N 384
#define G1A_FLOATS (G1_M * P36)              // 4608
#define G1B_FLOATS (G1_N * P36)              // 13824
#define G1STAGE    (G1A_FLOATS + G1B_FLOATS) // 18432 floats
#define G1SMEM_BYTES (3 * G1STAGE * 4)       // 221184 B
#define NCHUNK (KDIM / 32)                   // 32

__global__ __launch_bounds__(384, 1)
void gemm_tf32_384(const float* __restrict__ A, const float* __restrict__ Bt,
                   const float* __restrict__ bias, float* __restrict__ C)
{
    extern __shared__ float sm[];

    const int tid = threadIdx.x;
    const int wid = tid >> 5;
    const int lane = tid & 31;
    const int g = lane >> 2;
    const int t = lane & 3;
    const int wm = wid / 6;       // 0..1  -> 64 rows
    const int wn = wid % 6;       // 0..5  -> 64 cols

    const int m0 = blockIdx.y * G1_M;
    const int n0 = blockIdx.x * G1_N;

    const float* Abase = A  + (size_t)m0 * KDIM;
    const float* Bbase = Bt + (size_t)n0 * KDIM;
    const uint32_t smu = smem_u32(sm);

    // loader: A 128x32 = 1024 16B segs, B 384x32 = 3072 segs
    auto load_chunk = [&](int c, int st) {
        const int k0 = c * 32;
        const uint32_t sa = smu + (uint32_t)(st * G1STAGE) * 4u;
        const uint32_t sb = sa + (uint32_t)G1A_FLOATS * 4u;
#pragma unroll
        for (int i = 0; i < 3; ++i) {
            const int e = tid + 384 * i;           // 0..1151
            if (e < 1024) {
                const int r = e >> 3, q = e & 7;
                cp16(sa + (uint32_t)(r * P36 + q * 4) * 4u,
                     Abase + (size_t)r * KDIM + k0 + q * 4);
            }
        }
#pragma unroll
        for (int i = 0; i < 8; ++i) {
            const int e = tid + 384 * i;           // 0..3071
            const int r = e >> 3, q = e & 7;
            cp16(sb + (uint32_t)(r * P36 + q * 4) * 4u,
                 Bbase + (size_t)r * KDIM + k0 + q * 4);
        }
        CP_COMMIT();
    };

    float acc[4][8][4];
#pragma unroll
    for (int i = 0; i < 4; ++i)
#pragma unroll
        for (int j = 0; j < 8; ++j)
#pragma unroll
            for (int r = 0; r < 4; ++r) acc[i][j][r] = 0.f;

    load_chunk(0, 0);
    load_chunk(1, 1);

    for (int c = 0; c < NCHUNK; ++c) {
        const int s = c % 3;
        if (c + 1 < NCHUNK) CP_WAIT1(); else CP_WAIT0();
        __syncthreads();

        const float* As = sm + s * G1STAGE;
        const float* Bs = As + G1A_FLOATS;

#pragma unroll
        for (int ks = 0; ks < 4; ++ks) {
            const int koff = ks * 8;
            uint32_t bf[8][2];
#pragma unroll
            for (int nt = 0; nt < 8; ++nt) {
                const int nb = wn * 64 + nt * 8;
                bf[nt][0] = __float_as_uint(Bs[(nb + g) * P36 + koff + t]);
                bf[nt][1] = __float_as_uint(Bs[(nb + g) * P36 + koff + t + 4]);
            }
#pragma unroll
            for (int mt = 0; mt < 4; ++mt) {
                const int rb = wm * 64 + mt * 16;
                uint32_t af[4];
                af[0] = __float_as_uint(As[(rb + g)     * P36 + koff + t]);
                af[1] = __float_as_uint(As[(rb + g + 8) * P36 + koff + t]);
                af[2] = __float_as_uint(As[(rb + g)     * P36 + koff + t + 4]);
                af[3] = __float_as_uint(As[(rb + g + 8) * P36 + koff + t + 4]);
#pragma unroll
                for (int nt = 0; nt < 8; ++nt)
                    mma_tf32(acc[mt][nt], af, bf[nt]);
            }
        }

        if (c + 2 < NCHUNK) load_chunk(c + 2, (c + 2) % 3);
    }

    // Epilogue (tf32-rounded: feeds attention)
#pragma unroll
    for (int mt = 0; mt < 4; ++mt) {
        const int row = m0 + wm * 64 + mt * 16 + g;
#pragma unroll
        for (int nt = 0; nt < 8; ++nt) {
            const int col = n0 + wn * 64 + nt * 8 + t * 2;
            const float bx = __ldg(bias + col), by = __ldg(bias + col + 1);
            float2 lo = { round_tf32(acc[mt][nt][0] + bx), round_tf32(acc[mt][nt][1] + by) };
            float2 hi = { round_tf32(acc[mt][nt][2] + bx), round_tf32(acc[mt][nt][3] + by) };
            *(float2*)(C + (size_t)row * QKV_N + col)       = lo;
            *(float2*)(C + (size_t)(row + 8) * QKV_N + col) = hi;
        }
    }
}

// ---------------------------------------------------------------------------
// GEMM3 (round-5 wide kernel): tile 128x256, 8 warps, warp 64x64, 3-stage.
// ---------------------------------------------------------------------------
#define WBM 128
#define WBN 256
#define WA_FLOATS (WBM * P36)
#define WB_FLOATS (WBN * P36)
#define WSTAGE    (WA_FLOATS + WB_FLOATS)
#define WSMEM_BYTES (3 * WSTAGE * 4)

__global__ __launch_bounds__(256, 1)
void gemm_tf32_wide(const float* __restrict__ A, const float* __restrict__ Bt,
                    const float* __restrict__ bias, float* __restrict__ C, int Ntot)
{
    extern __shared__ float sm[];

    const int tid = threadIdx.x;
    const int wid = tid >> 5;
    const int lane = tid & 31;
    const int g = lane >> 2;
    const int t = lane & 3;
    const int wm = wid >> 2;
    const int wn = wid & 3;

    const int m0 = blockIdx.y * WBM;
    const int n0 = blockIdx.x * WBN;

    const float* Abase = A  + (size_t)m0 * KDIM;
    const float* Bbase = Bt + (size_t)n0 * KDIM;
    const uint32_t smu = smem_u32(sm);

    auto load_chunk = [&](int c, int st) {
        const int k0 = c * 32;
        const uint32_t sa = smu + (uint32_t)(st * WSTAGE) * 4u;
        const uint32_t sb = sa + (uint32_t)WA_FLOATS * 4u;
#pragma unroll
        for (int i = 0; i < 4; ++i) {
            const int e = tid + 256 * i;
            const int r = e >> 3, q = e & 7;
            cp16(sa + (uint32_t)(r * P36 + q * 4) * 4u, Abase + (size_t)r * KDIM + k0 + q * 4);
        }
#pragma unroll
        for (int i = 0; i < 8; ++i) {
            const int e = tid + 256 * i;
            const int r = e >> 3, q = e & 7;
            cp16(sb + (uint32_t)(r * P36 + q * 4) * 4u, Bbase + (size_t)r * KDIM + k0 + q * 4);
        }
        CP_COMMIT();
    };

    float acc[4][8][4];
#pragma unroll
    for (int i = 0; i < 4; ++i)
#pragma unroll
        for (int j = 0; j < 8; ++j)
#pragma unroll
            for (int r = 0; r < 4; ++r) acc[i][j][r] = 0.f;

    load_chunk(0, 0);
    load_chunk(1, 1);

    for (int c = 0; c < NCHUNK; ++c) {
        const int s = c % 3;
        if (c + 1 < NCHUNK) CP_WAIT1(); else CP_WAIT0();
        __syncthreads();

        const float* As = sm + s * WSTAGE;
        const float* Bs = As + WA_FLOATS;

#pragma unroll
        for (int ks = 0; ks < 4; ++ks) {
            const int koff = ks * 8;
            uint32_t af[4][4];
#pragma unroll
            for (int mt = 0; mt < 4; ++mt) {
                const int rb = wm * 64 + mt * 16;
                af[mt][0] = __float_as_uint(As[(rb + g)     * P36 + koff + t]);
                af[mt][1] = __float_as_uint(As[(rb + g + 8) * P36 + koff + t]);
                af[mt][2] = __float_as_uint(As[(rb + g)     * P36 + koff + t + 4]);
                af[mt][3] = __float_as_uint(As[(rb + g + 8) * P36 + koff + t + 4]);
            }
#pragma unroll
            for (int nt = 0; nt < 8; ++nt) {
                const int nb = wn * 64 + nt * 8;
                uint32_t bf[2];
                bf[0] = __float_as_uint(Bs[(nb + g) * P36 + koff + t]);
                bf[1] = __float_as_uint(Bs[(nb + g) * P36 + koff + t + 4]);
#pragma unroll
                for (int mt = 0; mt < 4; ++mt)
                    mma_tf32(acc[mt][nt], af[mt], bf);
            }
        }

        if (c + 2 < NCHUNK) load_chunk(c + 2, (c + 2) % 3);
    }

#pragma unroll
    for (int mt = 0; mt < 4; ++mt) {
        const int row = m0 + wm * 64 + mt * 16 + g;
#pragma unroll
        for (int nt = 0; nt < 8; ++nt) {
            const int col = n0 + wn * 64 + nt * 8 + t * 2;
            const float bx = __ldg(bias + col), by = __ldg(bias + col + 1);
            float2 lo = { acc[mt][nt][0] + bx, acc[mt][nt][1] + by };
            float2 hi = { acc[mt][nt][2] + bx, acc[mt][nt][3] + by };
            *(float2*)(C + (size_t)row * Ntot + col)       = lo;
            *(float2*)(C + (size_t)(row + 8) * Ntot + col) = hi;
        }
    }
}

// ---------------------------------------------------------------------------
// Preconditioning kernels
// ---------------------------------------------------------------------------
__global__ __launch_bounds__(256)
void transpose_round_kernel(const float* __restrict__ W, float* __restrict__ Wt, int N)
{
    __shared__ float tbuf[32][33];
    const int nb = blockIdx.x * 32, kb = blockIdx.y * 32;
    const int tx = threadIdx.x, ty = threadIdx.y;
#pragma unroll
    for (int i = 0; i < 32; i += 8)
        tbuf[ty + i][tx] = W[(size_t)(kb + ty + i) * N + nb + tx];
    __syncthreads();
#pragma unroll
    for (int i = 0; i < 32; i += 8)
        Wt[(size_t)(nb + ty + i) * KDIM + kb + tx] = round_tf32(tbuf[tx][ty + i]);
}

__global__ __launch_bounds__(256)
void round_x_kernel(const float* __restrict__ x, float* __restrict__ xr, int n4)
{
    int i = blockIdx.x * blockDim.x + threadIdx.x;
    if (i < n4) {
        float4 v = ((const float4*)x)[i];
        v.x = round_tf32(v.x); v.y = round_tf32(v.y);
        v.z = round_tf32(v.z); v.w = round_tf32(v.w);
        ((float4*)xr)[i] = v;
    }
}

// ---------------------------------------------------------------------------
// Tensor-core causal flash attention (round-5 version: 64-key tiles).
// CTA: one (b,h) x 128 q rows, 8 warps x 16 rows, warp-local softmax,
// P via warp-private smem; 2 CTAs/SM.
// ---------------------------------------------------------------------------
#define AQP 68
#define AVP 72
#define OFF_K  8704
#define OFF_V  13056
#define OFF_P  17664
#define ATT_SMEM_FLOATS 26368
#define ATT_SMEM_BYTES  (ATT_SMEM_FLOATS * 4)

__global__ __launch_bounds__(256)
void attn_mma_kernel(const float* __restrict__ qkv, float* __restrict__ out)
{
    extern __shared__ float sm[];
    const uint32_t smu = smem_u32(sm);

    const int tid = threadIdx.x;
    const int wid = tid >> 5;
    const int lane = tid & 31;
    const int g = lane >> 2, t = lane & 3;

    const int qt = gridDim.x - 1 - blockIdx.x;
    const int q0 = qt * 128;
    const int bh = blockIdx.y;
    const int b = bh >> 4, h = bh & 15;

    const float* base = qkv + (size_t)b * SEQ * QKV_N;

#pragma unroll
    for (int i = 0; i < 8; ++i) {
        const int e = tid + 256 * i;
        const int r = e >> 4, seg = e & 15;
        cp16(smu + (uint32_t)(r * AQP + seg * 4) * 4,
             base + (size_t)(q0 + r) * QKV_N + h * DH + seg * 4);
    }
    auto load_kv = [&](int k0) {
#pragma unroll
        for (int i = 0; i < 4; ++i) {
            const int e = tid + 256 * i;
            const int r = e >> 4, seg = e & 15;
            const float* krow = base + (size_t)(k0 + r) * QKV_N + DMODEL + h * DH + seg * 4;
            const float* vrow = base + (size_t)(k0 + r) * QKV_N + 2 * DMODEL + h * DH + seg * 4;
            cp16(smu + (uint32_t)(OFF_K + r * AQP + seg * 4) * 4, krow);
            cp16(smu + (uint32_t)(OFF_V + r * AVP + seg * 4) * 4, vrow);
        }
    };
    load_kv(0);
    CP_COMMIT(); CP_WAIT0();
    __syncthreads();

    const int niter = 2 * (qt + 1);
    const int row0 = wid * 16 + g;
    const int qrow0 = q0 + row0;
    const int qrow1 = qrow0 + 8;
    const float scale = 0.125f;

    float m0 = -INFINITY, m1 = -INFINITY, l0 = 0.f, l1 = 0.f;
    float accO[8][4];
#pragma unroll
    for (int nt = 0; nt < 8; ++nt)
#pragma unroll
        for (int r = 0; r < 4; ++r) accO[nt][r] = 0.f;

    for (int it = 0; it < niter; ++it) {
        const int k0 = it * 64;

        float accS[8][4];
#pragma unroll
        for (int nt = 0; nt < 8; ++nt)
#pragma unroll
            for (int r = 0; r < 4; ++r) accS[nt][r] = 0.f;

#pragma unroll
        for (int kd = 0; kd < 8; ++kd) {
            const int koff = kd * 8;
            uint32_t a[4];
            a[0] = __float_as_uint(sm[(row0)     * AQP + koff + t]);
            a[1] = __float_as_uint(sm[(row0 + 8) * AQP + koff + t]);
            a[2] = __float_as_uint(sm[(row0)     * AQP + koff + t + 4]);
            a[3] = __float_as_uint(sm[(row0 + 8) * AQP + koff + t + 4]);
#pragma unroll
            for (int nt = 0; nt < 8; ++nt) {
                uint32_t bf[2];
                bf[0] = __float_as_uint(sm[OFF_K + (nt * 8 + g) * AQP + koff + t]);
                bf[1] = __float_as_uint(sm[OFF_K + (nt * 8 + g) * AQP + koff + t + 4]);
                mma_tf32(accS[nt], a, bf);
            }
        }

        float pm0 = -INFINITY, pm1 = -INFINITY;
#pragma unroll
        for (int nt = 0; nt < 8; ++nt) {
            const int key = k0 + nt * 8 + 2 * t;
            accS[nt][0] = (key     <= qrow0) ? accS[nt][0] * scale : -INFINITY;
            accS[nt][1] = (key + 1 <= qrow0) ? accS[nt][1] * scale : -INFINITY;
            accS[nt][2] = (key     <= qrow1) ? accS[nt][2] * scale : -INFINITY;
            accS[nt][3] = (key + 1 <= qrow1) ? accS[nt][3] * scale : -INFINITY;
            pm0 = fmaxf(pm0, fmaxf(accS[nt][0], accS[nt][1]));
            pm1 = fmaxf(pm1, fmaxf(accS[nt][2], accS[nt][3]));
        }
        pm0 = fmaxf(pm0, __shfl_xor_sync(0xffffffffu, pm0, 1));
        pm0 = fmaxf(pm0, __shfl_xor_sync(0xffffffffu, pm0, 2));
        pm1 = fmaxf(pm1, __shfl_xor_sync(0xffffffffu, pm1, 1));
        pm1 = fmaxf(pm1, __shfl_xor_sync(0xffffffffu, pm1, 2));

        const float mn0 = fmaxf(m0, pm0), mn1 = fmaxf(m1, pm1);
        const float c0 = __expf(m0 - mn0), c1 = __expf(m1 - mn1);
        float ls0 = 0.f, ls1 = 0.f;
#pragma unroll
        for (int nt = 0; nt < 8; ++nt) {
            const float p0 = __expf(accS[nt][0] - mn0);
            const float p1 = __expf(accS[nt][1] - mn0);
            const float p2 = __expf(accS[nt][2] - mn1);
            const float p3 = __expf(accS[nt][3] - mn1);
            ls0 += p0 + p1; ls1 += p2 + p3;
            float2 lo = { round_tf32(p0), round_tf32(p1) };
            float2 hi = { round_tf32(p2), round_tf32(p3) };
            *(float2*)&sm[OFF_P + (row0)     * AQP + nt * 8 + 2 * t] = lo;
            *(float2*)&sm[OFF_P + (row0 + 8) * AQP + nt * 8 + 2 * t] = hi;
        }
        ls0 += __shfl_xor_sync(0xffffffffu, ls0, 1);
        ls0 += __shfl_xor_sync(0xffffffffu, ls0, 2);
        ls1 += __shfl_xor_sync(0xffffffffu, ls1, 1);
        ls1 += __shfl_xor_sync(0xffffffffu, ls1, 2);
        l0 = l0 * c0 + ls0;
        l1 = l1 * c1 + ls1;
        m0 = mn0; m1 = mn1;
#pragma unroll
        for (int nt = 0; nt < 8; ++nt) {
            accO[nt][0] *= c0; accO[nt][1] *= c0;
            accO[nt][2] *= c1; accO[nt][3] *= c1;
        }
        __syncwarp();

#pragma unroll
        for (int kc = 0; kc < 8; ++kc) {
            uint32_t a[4];
            a[0] = __float_as_uint(sm[OFF_P + (row0)     * AQP + kc * 8 + t]);
            a[1] = __float_as_uint(sm[OFF_P + (row0 + 8) * AQP + kc * 8 + t]);
            a[2] = __float_as_uint(sm[OFF_P + (row0)     * AQP + kc * 8 + t + 4]);
            a[3] = __float_as_uint(sm[OFF_P + (row0 + 8) * AQP + kc * 8 + t + 4]);
#pragma unroll
            for (int nt = 0; nt < 8; ++nt) {
                uint32_t bf[2];
                bf[0] = __float_as_uint(sm[OFF_V + (kc * 8 + t)     * AVP + nt * 8 + g]);
                bf[1] = __float_as_uint(sm[OFF_V + (kc * 8 + t + 4) * AVP + nt * 8 + g]);
                mma_tf32(accO[nt], a, bf);
            }
        }

        if (it + 1 < niter) {
            __syncthreads();
            load_kv(k0 + 64);
            CP_COMMIT(); CP_WAIT0();
            __syncthreads();
        }
    }

    const float rl0 = 1.0f / l0, rl1 = 1.0f / l1;
    float* o0 = out + (size_t)(b * SEQ + qrow0) * DMODEL + h * DH;
    float* o1 = out + (size_t)(b * SEQ + qrow1) * DMODEL + h * DH;
#pragma unroll
    for (int nt = 0; nt < 8; ++nt) {
        const int col = nt * 8 + 2 * t;
        float2 lo = { round_tf32(accO[nt][0] * rl0), round_tf32(accO[nt][1] * rl0) };
        float2 hi = { round_tf32(accO[nt][2] * rl1), round_tf32(accO[nt][3] * rl1) };
        *(float2*)(o0 + col) = lo;
        *(float2*)(o1 + col) = hi;
    }
}

// ---------------------------------------------------------------------------
// kernel_launch
// ---------------------------------------------------------------------------
extern "C" void kernel_launch(void* const* d_in, const int* in_sizes, int n_in,
                              void* d_out, int out_size)
{
    const float* x     = (const float*)d_in[0];
    const float* W_qkv = (const float*)d_in[1];
    const float* b_qkv = (const float*)d_in[2];
    const float* W_out = (const float*)d_in[3];
    const float* b_out = (const float*)d_in[4];
    float* out = (float*)d_out;

    float* qkv;  cudaGetSymbolAddress((void**)&qkv,  g_qkv);
    float* att;  cudaGetSymbolAddress((void**)&att,  g_att);
    float* xr;   cudaGetSymbolAddress((void**)&xr,   g_xr);
    float* wtq;  cudaGetSymbolAddress((void**)&wtq,  g_wt_qkv);
    float* wto;  cudaGetSymbolAddress((void**)&wto,  g_wt_out);

    cudaFuncSetAttribute(gemm_tf32_384,
                         cudaFuncAttributeMaxDynamicSharedMemorySize, G1SMEM_BYTES);
    cudaFuncSetAttribute(gemm_tf32_wide,
                         cudaFuncAttributeMaxDynamicSharedMemorySize, WSMEM_BYTES);
    cudaFuncSetAttribute(attn_mma_kernel,
                         cudaFuncAttributeMaxDynamicSharedMemorySize, ATT_SMEM_BYTES);

    // 0) precondition inputs to tf32
    {
        int n4 = MTOT * DMODEL / 4;
        round_x_kernel<<<(n4 + 255) / 256, 256>>>(x, xr, n4);
        transpose_round_kernel<<<dim3(QKV_N / 32, KDIM / 32), dim3(32, 8)>>>(W_qkv, wtq, QKV_N);
        transpose_round_kernel<<<dim3(DMODEL / 32, KDIM / 32), dim3(32, 8)>>>(W_out, wto, DMODEL);
    }
    // 1) QKV projection (12-warp GEMM), output rounded to tf32
    {
        dim3 grid(QKV_N / G1_N, MTOT / G1_M);   // (8, 64) = 512 CTAs
        gemm_tf32_384<<<grid, 384, G1SMEM_BYTES>>>(xr, wtq, b_qkv, qkv);
    }
    // 2) Causal attention (round-5 config)
    {
        dim3 grid(SEQ / 128, BATCH * NHEAD);    // (16, 64)
        attn_mma_kernel<<<grid, 256, ATT_SMEM_BYTES>>>(qkv, att);
    }
    // 3) Output projection, full fp32 output
    {
        dim3 grid(DMODEL / WBN, MTOT / WBM);    // (4, 64)
        gemm_tf32_wide<<<grid, 256, WSMEM_BYTES>>>(att, wto, b_out, out, DMODEL);
    }
}

// round 8
// speedup vs baseline: 1.0787x; 1.0662x over previous
#include <cuda_runtime.h>
#include <cuda_fp16.h>
#include <math.h>
#include <stdint.h>

// Problem constants
#define BATCH   4
#define SEQ     2048
#define DMODEL  1024
#define NHEAD   16
#define DH      64
#define MTOT    (BATCH * SEQ)       // 8192
#define QKV_N   (3 * DMODEL)        // 3072
#define KDIM    DMODEL

// ---------------------------------------------------------------------------
// Scratch (device globals: allocation-free rule)
// ---------------------------------------------------------------------------
__device__ __half g_qkv[(size_t)MTOT * QKV_N];     // [8192,3072] fp16
__device__ __half g_att[(size_t)MTOT * DMODEL];    // [8192,1024] fp16
__device__ __half g_xh[(size_t)MTOT * DMODEL];     // x -> fp16
__device__ __half g_wtq[(size_t)QKV_N * DMODEL];   // W_qkv^T fp16
__device__ __half g_wto[(size_t)DMODEL * DMODEL];  // W_out^T fp16

// ---------------------------------------------------------------------------
// Helpers (portable sm_80+ PTX only)
// ---------------------------------------------------------------------------
__device__ __forceinline__ uint32_t smem_u32(const void* p) {
    uint32_t a;
    asm("{ .reg .u64 t; cvta.to.shared.u64 t, %1; cvt.u32.u64 %0, t; }" : "=r"(a) : "l"(p));
    return a;
}
__device__ __forceinline__ void cp16(uint32_t dst, const void* src) {
    asm volatile("cp.async.cg.shared.global [%0], [%1], 16;" :: "r"(dst), "l"(src));
}
#define CP_COMMIT()  asm volatile("cp.async.commit_group;" ::: "memory")
#define CP_WAIT1()   asm volatile("cp.async.wait_group 1;" ::: "memory")
#define CP_WAIT0()   asm volatile("cp.async.wait_group 0;" ::: "memory")

// m16n8k16 fp16 mma, fp32 accumulate
__device__ __forceinline__ void mma_f16(float* d, const uint32_t* a, const uint32_t* b) {
    asm volatile(
        "mma.sync.aligned.m16n8k16.row.col.f32.f16.f16.f32 "
        "{%0,%1,%2,%3}, {%4,%5,%6,%7}, {%8,%9}, {%0,%1,%2,%3};"
        : "+f"(d[0]), "+f"(d[1]), "+f"(d[2]), "+f"(d[3])
        : "r"(a[0]), "r"(a[1]), "r"(a[2]), "r"(a[3]), "r"(b[0]), "r"(b[1]));
}
__device__ __forceinline__ uint32_t ldu32(const __half* p) {
    return *(const uint32_t*)p;
}
// pair of non-adjacent halves -> one register
__device__ __forceinline__ uint32_t hpair(const __half* p0, const __half* p1) {
    uint32_t lo = *(const uint16_t*)p0;
    uint32_t hi = *(const uint16_t*)p1;
    return lo | (hi << 16);
}

// ---------------------------------------------------------------------------
// fp16 GEMM: C[M,Ntot] = A[M,1024] @ Bt[Ntot,1024]^T + bias
// CTA 128x256, 8 warps (2x4), warp 64x64, BK=64 halves, 3-stage cp.async.
// Smem pitch 72 halves (36 words, ≡4 mod 32 -> conflict-free fragments).
// OUT_HALF=1: C is __half (rn). OUT_HALF=0: C is float.
// ---------------------------------------------------------------------------
#define PH 72
#define GBM 128
#define GBN 256
#define GA_HALVES (GBM * PH)                  // 9216
#define GB_HALVES (GBN * PH)                  // 18432
#define GSTAGE    (GA_HALVES + GB_HALVES)     // 27648 halves
#define GSMEM_BYTES (3 * GSTAGE * 2)          // 165888 B
#define NCHUNK (KDIM / 64)                    // 16

template <int OUT_HALF>
__global__ __launch_bounds__(256, 1)
void gemm_f16(const __half* __restrict__ A, const __half* __restrict__ Bt,
              const float* __restrict__ bias, void* __restrict__ Cv, int Ntot)
{
    extern __shared__ __align__(16) __half smh[];

    const int tid = threadIdx.x;
    const int wid = tid >> 5;
    const int lane = tid & 31;
    const int g = lane >> 2;
    const int t = lane & 3;
    const int wm = wid >> 2;
    const int wn = wid & 3;

    const int m0 = blockIdx.y * GBM;
    const int n0 = blockIdx.x * GBN;

    const __half* Abase = A  + (size_t)m0 * KDIM;
    const __half* Bbase = Bt + (size_t)n0 * KDIM;
    const uint32_t smu = smem_u32(smh);

    // loader: A 128 rows x 64 halves (8 segs/row) = 1024 segs; B 2048 segs
    auto load_chunk = [&](int c, int st) {
        const int k0 = c * 64;
        const uint32_t sa = smu + (uint32_t)(st * GSTAGE) * 2u;
        const uint32_t sb = sa + (uint32_t)GA_HALVES * 2u;
#pragma unroll
        for (int i = 0; i < 4; ++i) {
            const int e = tid + 256 * i;
            const int r = e >> 3, q = e & 7;
            cp16(sa + (uint32_t)(r * PH + q * 8) * 2u, Abase + (size_t)r * KDIM + k0 + q * 8);
        }
#pragma unroll
        for (int i = 0; i < 8; ++i) {
            const int e = tid + 256 * i;
            const int r = e >> 3, q = e & 7;
            cp16(sb + (uint32_t)(r * PH + q * 8) * 2u, Bbase + (size_t)r * KDIM + k0 + q * 8);
        }
        CP_COMMIT();
    };

    float acc[4][8][4];
#pragma unroll
    for (int i = 0; i < 4; ++i)
#pragma unroll
        for (int j = 0; j < 8; ++j)
#pragma unroll
            for (int r = 0; r < 4; ++r) acc[i][j][r] = 0.f;

    load_chunk(0, 0);
    load_chunk(1, 1);

    for (int c = 0; c < NCHUNK; ++c) {
        const int s = c % 3;
        if (c + 1 < NCHUNK) CP_WAIT1(); else CP_WAIT0();
        __syncthreads();

        const __half* As = smh + (size_t)s * GSTAGE;
        const __half* Bs = As + GA_HALVES;

#pragma unroll
        for (int ks = 0; ks < 4; ++ks) {
            const int koff = ks * 16;
            uint32_t af[4][4];
#pragma unroll
            for (int mt = 0; mt < 4; ++mt) {
                const int rb = wm * 64 + mt * 16;
                af[mt][0] = ldu32(As + (rb + g)     * PH + koff + 2 * t);
                af[mt][1] = ldu32(As + (rb + g + 8) * PH + koff + 2 * t);
                af[mt][2] = ldu32(As + (rb + g)     * PH + koff + 2 * t + 8);
                af[mt][3] = ldu32(As + (rb + g + 8) * PH + koff + 2 * t + 8);
            }
#pragma unroll
            for (int nt = 0; nt < 8; ++nt) {
                const int nb = wn * 64 + nt * 8;
                uint32_t bf[2];
                bf[0] = ldu32(Bs + (nb + g) * PH + koff + 2 * t);
                bf[1] = ldu32(Bs + (nb + g) * PH + koff + 2 * t + 8);
#pragma unroll
                for (int mt = 0; mt < 4; ++mt)
                    mma_f16(acc[mt][nt], af[mt], bf);
            }
        }

        if (c + 2 < NCHUNK) load_chunk(c + 2, (c + 2) % 3);
    }

    // Epilogue
#pragma unroll
    for (int mt = 0; mt < 4; ++mt) {
        const int row = m0 + wm * 64 + mt * 16 + g;
#pragma unroll
        for (int nt = 0; nt < 8; ++nt) {
            const int col = n0 + wn * 64 + nt * 8 + t * 2;
            const float bx = __ldg(bias + col), by = __ldg(bias + col + 1);
            if (OUT_HALF) {
                __half* C = (__half*)Cv;
                *(__half2*)(C + (size_t)row * Ntot + col) =
                    __floats2half2_rn(acc[mt][nt][0] + bx, acc[mt][nt][1] + by);
                *(__half2*)(C + (size_t)(row + 8) * Ntot + col) =
                    __floats2half2_rn(acc[mt][nt][2] + bx, acc[mt][nt][3] + by);
            } else {
                float* C = (float*)Cv;
                float2 lo = { acc[mt][nt][0] + bx, acc[mt][nt][1] + by };
                float2 hi = { acc[mt][nt][2] + bx, acc[mt][nt][3] + by };
                *(float2*)(C + (size_t)row * Ntot + col)       = lo;
                *(float2*)(C + (size_t)(row + 8) * Ntot + col) = hi;
            }
        }
    }
}

// ---------------------------------------------------------------------------
// Preconditioning kernels
// ---------------------------------------------------------------------------
__global__ __launch_bounds__(256)
void cvt_x_kernel(const float* __restrict__ x, __half* __restrict__ xh, int n4)
{
    int i = blockIdx.x * blockDim.x + threadIdx.x;
    if (i < n4) {
        float4 v = ((const float4*)x)[i];
        __half2 lo = __floats2half2_rn(v.x, v.y);
        __half2 hi = __floats2half2_rn(v.z, v.w);
        uint2 o = { *(uint32_t*)&lo, *(uint32_t*)&hi };
        ((uint2*)xh)[i] = o;
    }
}

__global__ __launch_bounds__(256)
void transpose_half_kernel(const float* __restrict__ W, __half* __restrict__ Wt, int N)
{
    __shared__ float tbuf[32][33];
    const int nb = blockIdx.x * 32, kb = blockIdx.y * 32;
    const int tx = threadIdx.x, ty = threadIdx.y;   // 32 x 8
#pragma unroll
    for (int i = 0; i < 32; i += 8)
        tbuf[ty + i][tx] = W[(size_t)(kb + ty + i) * N + nb + tx];
    __syncthreads();
#pragma unroll
    for (int i = 0; i < 32; i += 8)
        Wt[(size_t)(nb + ty + i) * KDIM + kb + tx] = __float2half_rn(tbuf[tx][ty + i]);
}

// ---------------------------------------------------------------------------
// fp16 tensor-core causal flash attention.
// CTA: one (b,h) x 128 q rows, 8 warps x 16 rows, warp-local softmax.
// 64-key tiles (round-5 structure). All operands fp16, fp32 accumulate.
// Smem (halves): Q[128][72], K[64][72], V[64][72], P[128][72]. 55.3 KB -> 2 CTA/SM.
// ---------------------------------------------------------------------------
#define AP 72
#define OFF_K  9216             // 128*72
#define OFF_V  13824            // +64*72
#define OFF_P  18432            // +64*72
#define ATT_SMEM_HALVES 27648   // +128*72
#define ATT_SMEM_BYTES  (ATT_SMEM_HALVES * 2)

__global__ __launch_bounds__(256)
void attn_f16_kernel(const __half* __restrict__ qkv, __half* __restrict__ out)
{
    extern __shared__ __align__(16) __half smh[];
    const uint32_t smu = smem_u32(smh);

    const int tid = threadIdx.x;
    const int wid = tid >> 5;
    const int lane = tid & 31;
    const int g = lane >> 2, t = lane & 3;

    const int qt = gridDim.x - 1 - blockIdx.x;   // heavy tiles first
    const int q0 = qt * 128;
    const int bh = blockIdx.y;
    const int b = bh >> 4, h = bh & 15;

    const __half* base = qkv + (size_t)b * SEQ * QKV_N;

    // stage Q: 128 rows x 64 halves = 1024 16B segs, 4 per thread
#pragma unroll
    for (int i = 0; i < 4; ++i) {
        const int e = tid + 256 * i;
        const int r = e >> 3, q = e & 7;
        cp16(smu + (uint32_t)(r * AP + q * 8) * 2u,
             base + (size_t)(q0 + r) * QKV_N + h * DH + q * 8);
    }
    auto load_kv = [&](int k0) {
#pragma unroll
        for (int i = 0; i < 2; ++i) {
            const int e = tid + 256 * i;       // 0..511
            const int r = e >> 3, q = e & 7;
            const __half* krow = base + (size_t)(k0 + r) * QKV_N + DMODEL + h * DH + q * 8;
            const __half* vrow = base + (size_t)(k0 + r) * QKV_N + 2 * DMODEL + h * DH + q * 8;
            cp16(smu + (uint32_t)(OFF_K + r * AP + q * 8) * 2u, krow);
            cp16(smu + (uint32_t)(OFF_V + r * AP + q * 8) * 2u, vrow);
        }
    };
    load_kv(0);
    CP_COMMIT(); CP_WAIT0();
    __syncthreads();

    const int niter = 2 * (qt + 1);
    const int row0 = wid * 16 + g;
    const int qrow0 = q0 + row0;
    const int qrow1 = qrow0 + 8;
    const float scale = 0.125f;

    float m0 = -INFINITY, m1 = -INFINITY, l0 = 0.f, l1 = 0.f;
    float accO[8][4];
#pragma unroll
    for (int nt = 0; nt < 8; ++nt)
#pragma unroll
        for (int r = 0; r < 4; ++r) accO[nt][r] = 0.f;

    const __half* Qs = smh;
    const __half* Ks = smh + OFF_K;
    const __half* Vs = smh + OFF_V;
    __half* Ps = smh + OFF_P;

    for (int it = 0; it < niter; ++it) {
        const int k0 = it * 64;

        // ---- S = Q K^T  (16 x 64 per warp; 4 k-steps of k=16) ----
        float accS[8][4];
#pragma unroll
        for (int nt = 0; nt < 8; ++nt)
#pragma unroll
            for (int r = 0; r < 4; ++r) accS[nt][r] = 0.f;

#pragma unroll
        for (int kd = 0; kd < 4; ++kd) {
            const int koff = kd * 16;
            uint32_t a[4];
            a[0] = ldu32(Qs + (row0)     * AP + koff + 2 * t);
            a[1] = ldu32(Qs + (row0 + 8) * AP + koff + 2 * t);
            a[2] = ldu32(Qs + (row0)     * AP + koff + 2 * t + 8);
            a[3] = ldu32(Qs + (row0 + 8) * AP + koff + 2 * t + 8);
#pragma unroll
            for (int nt = 0; nt < 8; ++nt) {
                uint32_t bf[2];
                bf[0] = ldu32(Ks + (nt * 8 + g) * AP + koff + 2 * t);
                bf[1] = ldu32(Ks + (nt * 8 + g) * AP + koff + 2 * t + 8);
                mma_f16(accS[nt], a, bf);
            }
        }

        // ---- scale + causal mask + online softmax ----
        float pm0 = -INFINITY, pm1 = -INFINITY;
#pragma unroll
        for (int nt = 0; nt < 8; ++nt) {
            const int key = k0 + nt * 8 + 2 * t;
            accS[nt][0] = (key     <= qrow0) ? accS[nt][0] * scale : -INFINITY;
            accS[nt][1] = (key + 1 <= qrow0) ? accS[nt][1] * scale : -INFINITY;
            accS[nt][2] = (key     <= qrow1) ? accS[nt][2] * scale : -INFINITY;
            accS[nt][3] = (key + 1 <= qrow1) ? accS[nt][3] * scale : -INFINITY;
            pm0 = fmaxf(pm0, fmaxf(accS[nt][0], accS[nt][1]));
            pm1 = fmaxf(pm1, fmaxf(accS[nt][2], accS[nt][3]));
        }
        pm0 = fmaxf(pm0, __shfl_xor_sync(0xffffffffu, pm0, 1));
        pm0 = fmaxf(pm0, __shfl_xor_sync(0xffffffffu, pm0, 2));
        pm1 = fmaxf(pm1, __shfl_xor_sync(0xffffffffu, pm1, 1));
        pm1 = fmaxf(pm1, __shfl_xor_sync(0xffffffffu, pm1, 2));

        const float mn0 = fmaxf(m0, pm0), mn1 = fmaxf(m1, pm1);
        const float c0 = __expf(m0 - mn0), c1 = __expf(m1 - mn1);
        float ls0 = 0.f, ls1 = 0.f;
#pragma unroll
        for (int nt = 0; nt < 8; ++nt) {
            const float p0 = __expf(accS[nt][0] - mn0);
            const float p1 = __expf(accS[nt][1] - mn0);
            const float p2 = __expf(accS[nt][2] - mn1);
            const float p3 = __expf(accS[nt][3] - mn1);
            ls0 += p0 + p1; ls1 += p2 + p3;
            *(__half2*)(Ps + (row0)     * AP + nt * 8 + 2 * t) = __floats2half2_rn(p0, p1);
            *(__half2*)(Ps + (row0 + 8) * AP + nt * 8 + 2 * t) = __floats2half2_rn(p2, p3);
        }
        ls0 += __shfl_xor_sync(0xffffffffu, ls0, 1);
        ls0 += __shfl_xor_sync(0xffffffffu, ls0, 2);
        ls1 += __shfl_xor_sync(0xffffffffu, ls1, 1);
        ls1 += __shfl_xor_sync(0xffffffffu, ls1, 2);
        l0 = l0 * c0 + ls0;
        l1 = l1 * c1 + ls1;
        m0 = mn0; m1 = mn1;
#pragma unroll
        for (int nt = 0; nt < 8; ++nt) {
            accO[nt][0] *= c0; accO[nt][1] *= c0;
            accO[nt][2] *= c1; accO[nt][3] *= c1;
        }
        __syncwarp();   // P tile is warp-private

        // ---- O += P V  (16 x 64 per warp; 4 k-steps of k=16 keys) ----
#pragma unroll
        for (int kc = 0; kc < 4; ++kc) {
            const int koff = kc * 16;
            uint32_t a[4];
            a[0] = ldu32(Ps + (row0)     * AP + koff + 2 * t);
            a[1] = ldu32(Ps + (row0 + 8) * AP + koff + 2 * t);
            a[2] = ldu32(Ps + (row0)     * AP + koff + 2 * t + 8);
            a[3] = ldu32(Ps + (row0 + 8) * AP + koff + 2 * t + 8);
#pragma unroll
            for (int nt = 0; nt < 8; ++nt) {
                const int d = nt * 8 + g;
                uint32_t bf[2];
                bf[0] = hpair(Vs + (koff + 2 * t)     * AP + d,
                              Vs + (koff + 2 * t + 1) * AP + d);
                bf[1] = hpair(Vs + (koff + 2 * t + 8) * AP + d,
                              Vs + (koff + 2 * t + 9) * AP + d);
                mma_f16(accO[nt], a, bf);
            }
        }

        if (it + 1 < niter) {
            __syncthreads();
            load_kv(k0 + 64);
            CP_COMMIT(); CP_WAIT0();
            __syncthreads();
        }
    }

    // ---- normalize + write fp16 (feeds fp16 out-proj) ----
    const float rl0 = 1.0f / l0, rl1 = 1.0f / l1;
    __half* o0 = out + (size_t)(b * SEQ + qrow0) * DMODEL + h * DH;
    __half* o1 = out + (size_t)(b * SEQ + qrow1) * DMODEL + h * DH;
#pragma unroll
    for (int nt = 0; nt < 8; ++nt) {
        const int col = nt * 8 + 2 * t;
        *(__half2*)(o0 + col) = __floats2half2_rn(accO[nt][0] * rl0, accO[nt][1] * rl0);
        *(__half2*)(o1 + col) = __floats2half2_rn(accO[nt][2] * rl1, accO[nt][3] * rl1);
    }
}

// ---------------------------------------------------------------------------
// kernel_launch
// ---------------------------------------------------------------------------
extern "C" void kernel_launch(void* const* d_in, const int* in_sizes, int n_in,
                              void* d_out, int out_size)
{
    const float* x     = (const float*)d_in[0];
    const float* W_qkv = (const float*)d_in[1];
    const float* b_qkv = (const float*)d_in[2];
    const float* W_out = (const float*)d_in[3];
    const float* b_out = (const float*)d_in[4];
    float* out = (float*)d_out;

    __half* qkv; cudaGetSymbolAddress((void**)&qkv, g_qkv);
    __half* att; cudaGetSymbolAddress((void**)&att, g_att);
    __half* xh;  cudaGetSymbolAddress((void**)&xh,  g_xh);
    __half* wtq; cudaGetSymbolAddress((void**)&wtq, g_wtq);
    __half* wto; cudaGetSymbolAddress((void**)&wto, g_wto);

    cudaFuncSetAttribute(gemm_f16<1>,
                         cudaFuncAttributeMaxDynamicSharedMemorySize, GSMEM_BYTES);
    cudaFuncSetAttribute(gemm_f16<0>,
                         cudaFuncAttributeMaxDynamicSharedMemorySize, GSMEM_BYTES);
    cudaFuncSetAttribute(attn_f16_kernel,
                         cudaFuncAttributeMaxDynamicSharedMemorySize, ATT_SMEM_BYTES);

    // 0) precondition inputs to fp16
    {
        int n4 = MTOT * DMODEL / 4;
        cvt_x_kernel<<<(n4 + 255) / 256, 256>>>(x, xh, n4);
        transpose_half_kernel<<<dim3(QKV_N / 32, KDIM / 32), dim3(32, 8)>>>(W_qkv, wtq, QKV_N);
        transpose_half_kernel<<<dim3(DMODEL / 32, KDIM / 32), dim3(32, 8)>>>(W_out, wto, DMODEL);
    }
    // 1) QKV projection (fp16 mma), output fp16
    {
        dim3 grid(QKV_N / GBN, MTOT / GBM);   // (12, 64)
        gemm_f16<1><<<grid, 256, GSMEM_BYTES>>>(xh, wtq, b_qkv, qkv, QKV_N);
    }
    // 2) Causal attention (fp16 mma)
    {
        dim3 grid(SEQ / 128, BATCH * NHEAD);  // (16, 64)
        attn_f16_kernel<<<grid, 256, ATT_SMEM_BYTES>>>(qkv, att);
    }
    // 3) Output projection (fp16 mma), fp32 output
    {
        dim3 grid(DMODEL / GBN, MTOT / GBM);  // (4, 64)
        gemm_f16<0><<<grid, 256, GSMEM_BYTES>>>(att, wto, b_out, out, DMODEL);
    }
}

// round 9
// speedup vs baseline: 1.8458x; 1.7111x over previous
#include <cuda_runtime.h>
#include <cuda_fp16.h>
#include <math.h>
#include <stdint.h>

// Problem constants
#define BATCH   4
#define SEQ     2048
#define DMODEL  1024
#define NHEAD   16
#define DH      64
#define MTOT    (BATCH * SEQ)       // 8192
#define QKV_N   (3 * DMODEL)        // 3072
#define KDIM    DMODEL

// ---------------------------------------------------------------------------
// Scratch (device globals: allocation-free rule)
// ---------------------------------------------------------------------------
__device__ __half g_qkv[(size_t)MTOT * QKV_N];     // [8192,3072] fp16
__device__ __half g_att[(size_t)MTOT * DMODEL];    // [8192,1024] fp16
__device__ __half g_xh[(size_t)MTOT * DMODEL];     // x -> fp16
__device__ __half g_wtq[(size_t)QKV_N * DMODEL];   // W_qkv^T fp16
__device__ __half g_wto[(size_t)DMODEL * DMODEL];  // W_out^T fp16

// ---------------------------------------------------------------------------
// Helpers (portable sm_80+ PTX only)
// ---------------------------------------------------------------------------
__device__ __forceinline__ uint32_t smem_u32(const void* p) {
    uint32_t a;
    asm("{ .reg .u64 t; cvta.to.shared.u64 t, %1; cvt.u32.u64 %0, t; }" : "=r"(a) : "l"(p));
    return a;
}
__device__ __forceinline__ void cp16(uint32_t dst, const void* src) {
    asm volatile("cp.async.cg.shared.global [%0], [%1], 16;" :: "r"(dst), "l"(src));
}
#define CP_COMMIT()  asm volatile("cp.async.commit_group;" ::: "memory")
#define CP_WAIT1()   asm volatile("cp.async.wait_group 1;" ::: "memory")
#define CP_WAIT0()   asm volatile("cp.async.wait_group 0;" ::: "memory")

__device__ __forceinline__ void mma_f16(float* d, const uint32_t* a, const uint32_t* b) {
    asm volatile(
        "mma.sync.aligned.m16n8k16.row.col.f32.f16.f16.f32 "
        "{%0,%1,%2,%3}, {%4,%5,%6,%7}, {%8,%9}, {%0,%1,%2,%3};"
        : "+f"(d[0]), "+f"(d[1]), "+f"(d[2]), "+f"(d[3])
        : "r"(a[0]), "r"(a[1]), "r"(a[2]), "r"(a[3]), "r"(b[0]), "r"(b[1]));
}
__device__ __forceinline__ uint32_t ldu32(const __half* p) {
    return *(const uint32_t*)p;
}
__device__ __forceinline__ void ldsm_x4_trans(uint32_t& r0, uint32_t& r1,
                                              uint32_t& r2, uint32_t& r3, uint32_t addr) {
    asm volatile("ldmatrix.sync.aligned.m8n8.x4.trans.shared.b16 {%0,%1,%2,%3}, [%4];"
                 : "=r"(r0), "=r"(r1), "=r"(r2), "=r"(r3) : "r"(addr));
}
// pack two f32 -> f16x2 (lo = a, hi = b), then exp2 both halves in one MUFU op
__device__ __forceinline__ uint32_t exp2_f16x2(float lo, float hi) {
    uint32_t h, p;
    asm("cvt.rn.f16x2.f32 %0, %1, %2;" : "=r"(h) : "f"(hi), "f"(lo));
    asm("ex2.approx.f16x2 %0, %1;" : "=r"(p) : "r"(h));
    return p;
}
__device__ __forceinline__ float exp2_f32(float x) {
    float r;
    asm("ex2.approx.f32 %0, %1;" : "=f"(r) : "f"(x));
    return r;
}

// ---------------------------------------------------------------------------
// GEMM1: fp16, 384 threads (12 warps, 2x6), tile 128x384, warp 64x64, BK=64.
// 3-stage cp.async. Output __half (rn), N fixed = QKV_N.
// Smem pitch 72 halves (36 words ≡ 4 mod 32 -> conflict-free fragment LDS).
// ---------------------------------------------------------------------------
#define PH 72
#define G1_M 128
#define G1_N 384
#define G1A_HALVES (G1_M * PH)                 // 9216
#define G1B_HALVES (G1_N * PH)                 // 27648
#define G1STAGE    (G1A_HALVES + G1B_HALVES)   // 36864 halves
#define G1SMEM_BYTES (3 * G1STAGE * 2)         // 221184 B
#define NCHUNK (KDIM / 64)                     // 16

__global__ __launch_bounds__(384, 1)
void gemm_f16_384(const __half* __restrict__ A, const __half* __restrict__ Bt,
                  const float* __restrict__ bias, __half* __restrict__ C)
{
    extern __shared__ __align__(16) __half smh[];

    const int tid = threadIdx.x;
    const int wid = tid >> 5;
    const int lane = tid & 31;
    const int g = lane >> 2;
    const int t = lane & 3;
    const int wm = wid / 6;       // 0..1
    const int wn = wid % 6;       // 0..5

    const int m0 = blockIdx.y * G1_M;
    const int n0 = blockIdx.x * G1_N;

    const __half* Abase = A  + (size_t)m0 * KDIM;
    const __half* Bbase = Bt + (size_t)n0 * KDIM;
    const uint32_t smu = smem_u32(smh);

    // A: 128 rows x 8 segs = 1024; B: 384 x 8 = 3072
    auto load_chunk = [&](int c, int st) {
        const int k0 = c * 64;
        const uint32_t sa = smu + (uint32_t)(st * G1STAGE) * 2u;
        const uint32_t sb = sa + (uint32_t)G1A_HALVES * 2u;
#pragma unroll
        for (int i = 0; i < 3; ++i) {
            const int e = tid + 384 * i;
            if (e < 1024) {
                const int r = e >> 3, q = e & 7;
                cp16(sa + (uint32_t)(r * PH + q * 8) * 2u,
                     Abase + (size_t)r * KDIM + k0 + q * 8);
            }
        }
#pragma unroll
        for (int i = 0; i < 8; ++i) {
            const int e = tid + 384 * i;
            const int r = e >> 3, q = e & 7;
            cp16(sb + (uint32_t)(r * PH + q * 8) * 2u,
                 Bbase + (size_t)r * KDIM + k0 + q * 8);
        }
        CP_COMMIT();
    };

    float acc[4][8][4];
#pragma unroll
    for (int i = 0; i < 4; ++i)
#pragma unroll
        for (int j = 0; j < 8; ++j)
#pragma unroll
            for (int r = 0; r < 4; ++r) acc[i][j][r] = 0.f;

    load_chunk(0, 0);
    load_chunk(1, 1);

    for (int c = 0; c < NCHUNK; ++c) {
        const int s = c % 3;
        if (c + 1 < NCHUNK) CP_WAIT1(); else CP_WAIT0();
        __syncthreads();

        const __half* As = smh + (size_t)s * G1STAGE;
        const __half* Bs = As + G1A_HALVES;

#pragma unroll
        for (int ks = 0; ks < 4; ++ks) {
            const int koff = ks * 16;
            uint32_t bf[8][2];
#pragma unroll
            for (int nt = 0; nt < 8; ++nt) {
                const int nb = wn * 64 + nt * 8;
                bf[nt][0] = ldu32(Bs + (nb + g) * PH + koff + 2 * t);
                bf[nt][1] = ldu32(Bs + (nb + g) * PH + koff + 2 * t + 8);
            }
#pragma unroll
            for (int mt = 0; mt < 4; ++mt) {
                const int rb = wm * 64 + mt * 16;
                uint32_t af[4];
                af[0] = ldu32(As + (rb + g)     * PH + koff + 2 * t);
                af[1] = ldu32(As + (rb + g + 8) * PH + koff + 2 * t);
                af[2] = ldu32(As + (rb + g)     * PH + koff + 2 * t + 8);
                af[3] = ldu32(As + (rb + g + 8) * PH + koff + 2 * t + 8);
#pragma unroll
                for (int nt = 0; nt < 8; ++nt)
                    mma_f16(acc[mt][nt], af, bf[nt]);
            }
        }

        if (c + 2 < NCHUNK) load_chunk(c + 2, (c + 2) % 3);
    }

#pragma unroll
    for (int mt = 0; mt < 4; ++mt) {
        const int row = m0 + wm * 64 + mt * 16 + g;
#pragma unroll
        for (int nt = 0; nt < 8; ++nt) {
            const int col = n0 + wn * 64 + nt * 8 + t * 2;
            const float bx = __ldg(bias + col), by = __ldg(bias + col + 1);
            *(__half2*)(C + (size_t)row * QKV_N + col) =
                __floats2half2_rn(acc[mt][nt][0] + bx, acc[mt][nt][1] + by);
            *(__half2*)(C + (size_t)(row + 8) * QKV_N + col) =
                __floats2half2_rn(acc[mt][nt][2] + bx, acc[mt][nt][3] + by);
        }
    }
}

// ---------------------------------------------------------------------------
// GEMM3: fp16, 256 threads, tile 128x256, warp 64x64 (round-8 kernel), f32 out.
// ---------------------------------------------------------------------------
#define GBM 128
#define GBN 256
#define GA_HALVES (GBM * PH)
#define GB_HALVES (GBN * PH)
#define GSTAGE    (GA_HALVES + GB_HALVES)
#define GSMEM_BYTES (3 * GSTAGE * 2)

__global__ __launch_bounds__(256, 1)
void gemm_f16_wide(const __half* __restrict__ A, const __half* __restrict__ Bt,
                   const float* __restrict__ bias, float* __restrict__ C, int Ntot)
{
    extern __shared__ __align__(16) __half smh[];

    const int tid = threadIdx.x;
    const int wid = tid >> 5;
    const int lane = tid & 31;
    const int g = lane >> 2;
    const int t = lane & 3;
    const int wm = wid >> 2;
    const int wn = wid & 3;

    const int m0 = blockIdx.y * GBM;
    const int n0 = blockIdx.x * GBN;

    const __half* Abase = A  + (size_t)m0 * KDIM;
    const __half* Bbase = Bt + (size_t)n0 * KDIM;
    const uint32_t smu = smem_u32(smh);

    auto load_chunk = [&](int c, int st) {
        const int k0 = c * 64;
        const uint32_t sa = smu + (uint32_t)(st * GSTAGE) * 2u;
        const uint32_t sb = sa + (uint32_t)GA_HALVES * 2u;
#pragma unroll
        for (int i = 0; i < 4; ++i) {
            const int e = tid + 256 * i;
            const int r = e >> 3, q = e & 7;
            cp16(sa + (uint32_t)(r * PH + q * 8) * 2u, Abase + (size_t)r * KDIM + k0 + q * 8);
        }
#pragma unroll
        for (int i = 0; i < 8; ++i) {
            const int e = tid + 256 * i;
            const int r = e >> 3, q = e & 7;
            cp16(sb + (uint32_t)(r * PH + q * 8) * 2u, Bbase + (size_t)r * KDIM + k0 + q * 8);
        }
        CP_COMMIT();
    };

    float acc[4][8][4];
#pragma unroll
    for (int i = 0; i < 4; ++i)
#pragma unroll
        for (int j = 0; j < 8; ++j)
#pragma unroll
            for (int r = 0; r < 4; ++r) acc[i][j][r] = 0.f;

    load_chunk(0, 0);
    load_chunk(1, 1);

    for (int c = 0; c < NCHUNK; ++c) {
        const int s = c % 3;
        if (c + 1 < NCHUNK) CP_WAIT1(); else CP_WAIT0();
        __syncthreads();

        const __half* As = smh + (size_t)s * GSTAGE;
        const __half* Bs = As + GA_HALVES;

#pragma unroll
        for (int ks = 0; ks < 4; ++ks) {
            const int koff = ks * 16;
            uint32_t af[4][4];
#pragma unroll
            for (int mt = 0; mt < 4; ++mt) {
                const int rb = wm * 64 + mt * 16;
                af[mt][0] = ldu32(As + (rb + g)     * PH + koff + 2 * t);
                af[mt][1] = ldu32(As + (rb + g + 8) * PH + koff + 2 * t);
                af[mt][2] = ldu32(As + (rb + g)     * PH + koff + 2 * t + 8);
                af[mt][3] = ldu32(As + (rb + g + 8) * PH + koff + 2 * t + 8);
            }
#pragma unroll
            for (int nt = 0; nt < 8; ++nt) {
                const int nb = wn * 64 + nt * 8;
                uint32_t bf[2];
                bf[0] = ldu32(Bs + (nb + g) * PH + koff + 2 * t);
                bf[1] = ldu32(Bs + (nb + g) * PH + koff + 2 * t + 8);
#pragma unroll
                for (int mt = 0; mt < 4; ++mt)
                    mma_f16(acc[mt][nt], af[mt], bf);
            }
        }

        if (c + 2 < NCHUNK) load_chunk(c + 2, (c + 2) % 3);
    }

#pragma unroll
    for (int mt = 0; mt < 4; ++mt) {
        const int row = m0 + wm * 64 + mt * 16 + g;
#pragma unroll
        for (int nt = 0; nt < 8; ++nt) {
            const int col = n0 + wn * 64 + nt * 8 + t * 2;
            const float bx = __ldg(bias + col), by = __ldg(bias + col + 1);
            float2 lo = { acc[mt][nt][0] + bx, acc[mt][nt][1] + by };
            float2 hi = { acc[mt][nt][2] + bx, acc[mt][nt][3] + by };
            *(float2*)(C + (size_t)row * Ntot + col)       = lo;
            *(float2*)(C + (size_t)(row + 8) * Ntot + col) = hi;
        }
    }
}

// ---------------------------------------------------------------------------
// Preconditioning kernels
// ---------------------------------------------------------------------------
__global__ __launch_bounds__(256)
void cvt_x_kernel(const float* __restrict__ x, __half* __restrict__ xh, int n4)
{
    int i = blockIdx.x * blockDim.x + threadIdx.x;
    if (i < n4) {
        float4 v = ((const float4*)x)[i];
        __half2 lo = __floats2half2_rn(v.x, v.y);
        __half2 hi = __floats2half2_rn(v.z, v.w);
        uint2 o = { *(uint32_t*)&lo, *(uint32_t*)&hi };
        ((uint2*)xh)[i] = o;
    }
}

__global__ __launch_bounds__(256)
void transpose_half_kernel(const float* __restrict__ W, __half* __restrict__ Wt, int N)
{
    __shared__ float tbuf[32][33];
    const int nb = blockIdx.x * 32, kb = blockIdx.y * 32;
    const int tx = threadIdx.x, ty = threadIdx.y;
#pragma unroll
    for (int i = 0; i < 32; i += 8)
        tbuf[ty + i][tx] = W[(size_t)(kb + ty + i) * N + nb + tx];
    __syncthreads();
#pragma unroll
    for (int i = 0; i < 32; i += 8)
        Wt[(size_t)(nb + ty + i) * KDIM + kb + tx] = __float2half_rn(tbuf[tx][ty + i]);
}

// ---------------------------------------------------------------------------
// fp16 tensor-core causal flash attention.
// 64-key tiles. V B-fragments via ldmatrix.x4.trans; softmax via ex2.f16x2
// in log2 domain. CTA: one (b,h) x 128 q rows, 8 warps x 16 rows.
// ---------------------------------------------------------------------------
#define AP 72
#define OFF_K  9216
#define OFF_V  13824
#define OFF_P  18432
#define ATT_SMEM_HALVES 27648
#define ATT_SMEM_BYTES  (ATT_SMEM_HALVES * 2)

__global__ __launch_bounds__(256)
void attn_f16_kernel(const __half* __restrict__ qkv, __half* __restrict__ out)
{
    extern __shared__ __align__(16) __half smh[];
    const uint32_t smu = smem_u32(smh);

    const int tid = threadIdx.x;
    const int wid = tid >> 5;
    const int lane = tid & 31;
    const int g = lane >> 2, t = lane & 3;

    const int qt = gridDim.x - 1 - blockIdx.x;   // heavy tiles first
    const int q0 = qt * 128;
    const int bh = blockIdx.y;
    const int b = bh >> 4, h = bh & 15;

    const __half* base = qkv + (size_t)b * SEQ * QKV_N;

#pragma unroll
    for (int i = 0; i < 4; ++i) {
        const int e = tid + 256 * i;
        const int r = e >> 3, q = e & 7;
        cp16(smu + (uint32_t)(r * AP + q * 8) * 2u,
             base + (size_t)(q0 + r) * QKV_N + h * DH + q * 8);
    }
    auto load_kv = [&](int k0) {
#pragma unroll
        for (int i = 0; i < 2; ++i) {
            const int e = tid + 256 * i;
            const int r = e >> 3, q = e & 7;
            const __half* krow = base + (size_t)(k0 + r) * QKV_N + DMODEL + h * DH + q * 8;
            const __half* vrow = base + (size_t)(k0 + r) * QKV_N + 2 * DMODEL + h * DH + q * 8;
            cp16(smu + (uint32_t)(OFF_K + r * AP + q * 8) * 2u, krow);
            cp16(smu + (uint32_t)(OFF_V + r * AP + q * 8) * 2u, vrow);
        }
    };
    load_kv(0);
    CP_COMMIT(); CP_WAIT0();
    __syncthreads();

    const int niter = 2 * (qt + 1);
    const int row0 = wid * 16 + g;
    const int qrow0 = q0 + row0;
    const int qrow1 = qrow0 + 8;
    const float l2s = 0.1803368801111204f;   // (1/8) * log2(e)

    // ldmatrix V address base: lane -> row (lane&15), col-block (lane>>4)*8
    const uint32_t vbase = smu +
        (uint32_t)((OFF_V + (lane & 15) * AP + ((lane >> 4) << 3)) * 2);

    float m0 = -INFINITY, m1 = -INFINITY, l0 = 0.f, l1 = 0.f;
    float accO[8][4];
#pragma unroll
    for (int nt = 0; nt < 8; ++nt)
#pragma unroll
        for (int r = 0; r < 4; ++r) accO[nt][r] = 0.f;

    const __half* Qs = smh;
    const __half* Ks = smh + OFF_K;
    __half* Ps = smh + OFF_P;

    for (int it = 0; it < niter; ++it) {
        const int k0 = it * 64;

        // ---- S = Q K^T ----
        float accS[8][4];
#pragma unroll
        for (int nt = 0; nt < 8; ++nt)
#pragma unroll
            for (int r = 0; r < 4; ++r) accS[nt][r] = 0.f;

#pragma unroll
        for (int kd = 0; kd < 4; ++kd) {
            const int koff = kd * 16;
            uint32_t a[4];
            a[0] = ldu32(Qs + (row0)     * AP + koff + 2 * t);
            a[1] = ldu32(Qs + (row0 + 8) * AP + koff + 2 * t);
            a[2] = ldu32(Qs + (row0)     * AP + koff + 2 * t + 8);
            a[3] = ldu32(Qs + (row0 + 8) * AP + koff + 2 * t + 8);
#pragma unroll
            for (int nt = 0; nt < 8; ++nt) {
                uint32_t bf[2];
                bf[0] = ldu32(Ks + (nt * 8 + g) * AP + koff + 2 * t);
                bf[1] = ldu32(Ks + (nt * 8 + g) * AP + koff + 2 * t + 8);
                mma_f16(accS[nt], a, bf);
            }
        }

        // ---- mask + online softmax in log2 domain ----
        float pm0 = -INFINITY, pm1 = -INFINITY;
#pragma unroll
        for (int nt = 0; nt < 8; ++nt) {
            const int key = k0 + nt * 8 + 2 * t;
            accS[nt][0] = (key     <= qrow0) ? accS[nt][0] * l2s : -INFINITY;
            accS[nt][1] = (key + 1 <= qrow0) ? accS[nt][1] * l2s : -INFINITY;
            accS[nt][2] = (key     <= qrow1) ? accS[nt][2] * l2s : -INFINITY;
            accS[nt][3] = (key + 1 <= qrow1) ? accS[nt][3] * l2s : -INFINITY;
            pm0 = fmaxf(pm0, fmaxf(accS[nt][0], accS[nt][1]));
            pm1 = fmaxf(pm1, fmaxf(accS[nt][2], accS[nt][3]));
        }
        pm0 = fmaxf(pm0, __shfl_xor_sync(0xffffffffu, pm0, 1));
        pm0 = fmaxf(pm0, __shfl_xor_sync(0xffffffffu, pm0, 2));
        pm1 = fmaxf(pm1, __shfl_xor_sync(0xffffffffu, pm1, 1));
        pm1 = fmaxf(pm1, __shfl_xor_sync(0xffffffffu, pm1, 2));

        const float mn0 = fmaxf(m0, pm0), mn1 = fmaxf(m1, pm1);
        const float c0 = exp2_f32(m0 - mn0), c1 = exp2_f32(m1 - mn1);
        float ls0 = 0.f, ls1 = 0.f;
#pragma unroll
        for (int nt = 0; nt < 8; ++nt) {
            const uint32_t p01 = exp2_f16x2(accS[nt][0] - mn0, accS[nt][1] - mn0);
            const uint32_t p23 = exp2_f16x2(accS[nt][2] - mn1, accS[nt][3] - mn1);
            *(uint32_t*)(Ps + (row0)     * AP + nt * 8 + 2 * t) = p01;
            *(uint32_t*)(Ps + (row0 + 8) * AP + nt * 8 + 2 * t) = p23;
            const float2 f01 = __half22float2(*(const __half2*)&p01);
            const float2 f23 = __half22float2(*(const __half2*)&p23);
            ls0 += f01.x + f01.y;
            ls1 += f23.x + f23.y;
        }
        ls0 += __shfl_xor_sync(0xffffffffu, ls0, 1);
        ls0 += __shfl_xor_sync(0xffffffffu, ls0, 2);
        ls1 += __shfl_xor_sync(0xffffffffu, ls1, 1);
        ls1 += __shfl_xor_sync(0xffffffffu, ls1, 2);
        l0 = l0 * c0 + ls0;
        l1 = l1 * c1 + ls1;
        m0 = mn0; m1 = mn1;
#pragma unroll
        for (int nt = 0; nt < 8; ++nt) {
            accO[nt][0] *= c0; accO[nt][1] *= c0;
            accO[nt][2] *= c1; accO[nt][3] *= c1;
        }
        __syncwarp();   // P tile is warp-private

        // ---- O += P V  (V B-fragments via ldmatrix.x4.trans) ----
#pragma unroll
        for (int kc = 0; kc < 4; ++kc) {
            const int koff = kc * 16;
            uint32_t a[4];
            a[0] = ldu32(Ps + (row0)     * AP + koff + 2 * t);
            a[1] = ldu32(Ps + (row0 + 8) * AP + koff + 2 * t);
            a[2] = ldu32(Ps + (row0)     * AP + koff + 2 * t + 8);
            a[3] = ldu32(Ps + (row0 + 8) * AP + koff + 2 * t + 8);
#pragma unroll
            for (int ntp = 0; ntp < 4; ++ntp) {
                uint32_t b0, b1, b2, b3;
                ldsm_x4_trans(b0, b1, b2, b3,
                              vbase + (uint32_t)((koff * AP + ntp * 16) * 2));
                uint32_t bf0[2] = { b0, b1 };
                uint32_t bf1[2] = { b2, b3 };
                mma_f16(accO[2 * ntp],     a, bf0);
                mma_f16(accO[2 * ntp + 1], a, bf1);
            }
        }

        if (it + 1 < niter) {
            __syncthreads();
            load_kv(k0 + 64);
            CP_COMMIT(); CP_WAIT0();
            __syncthreads();
        }
    }

    // ---- normalize + write fp16 ----
    const float rl0 = 1.0f / l0, rl1 = 1.0f / l1;
    __half* o0 = out + (size_t)(b * SEQ + qrow0) * DMODEL + h * DH;
    __half* o1 = out + (size_t)(b * SEQ + qrow1) * DMODEL + h * DH;
#pragma unroll
    for (int nt = 0; nt < 8; ++nt) {
        const int col = nt * 8 + 2 * t;
        *(__half2*)(o0 + col) = __floats2half2_rn(accO[nt][0] * rl0, accO[nt][1] * rl0);
        *(__half2*)(o1 + col) = __floats2half2_rn(accO[nt][2] * rl1, accO[nt][3] * rl1);
    }
}

// ---------------------------------------------------------------------------
// kernel_launch
// ---------------------------------------------------------------------------
extern "C" void kernel_launch(void* const* d_in, const int* in_sizes, int n_in,
                              void* d_out, int out_size)
{
    const float* x     = (const float*)d_in[0];
    const float* W_qkv = (const float*)d_in[1];
    const float* b_qkv = (const float*)d_in[2];
    const float* W_out = (const float*)d_in[3];
    const float* b_out = (const float*)d_in[4];
    float* out = (float*)d_out;

    __half* qkv; cudaGetSymbolAddress((void**)&qkv, g_qkv);
    __half* att; cudaGetSymbolAddress((void**)&att, g_att);
    __half* xh;  cudaGetSymbolAddress((void**)&xh,  g_xh);
    __half* wtq; cudaGetSymbolAddress((void**)&wtq, g_wtq);
    __half* wto; cudaGetSymbolAddress((void**)&wto, g_wto);

    cudaFuncSetAttribute(gemm_f16_384,
                         cudaFuncAttributeMaxDynamicSharedMemorySize, G1SMEM_BYTES);
    cudaFuncSetAttribute(gemm_f16_wide,
                         cudaFuncAttributeMaxDynamicSharedMemorySize, GSMEM_BYTES);
    cudaFuncSetAttribute(attn_f16_kernel,
                         cudaFuncAttributeMaxDynamicSharedMemorySize, ATT_SMEM_BYTES);

    // 0) precondition inputs to fp16
    {
        int n4 = MTOT * DMODEL / 4;
        cvt_x_kernel<<<(n4 + 255) / 256, 256>>>(x, xh, n4);
        transpose_half_kernel<<<dim3(QKV_N / 32, KDIM / 32), dim3(32, 8)>>>(W_qkv, wtq, QKV_N);
        transpose_half_kernel<<<dim3(DMODEL / 32, KDIM / 32), dim3(32, 8)>>>(W_out, wto, DMODEL);
    }
    // 1) QKV projection (12-warp fp16), output fp16
    {
        dim3 grid(QKV_N / G1_N, MTOT / G1_M);   // (8, 64)
        gemm_f16_384<<<grid, 384, G1SMEM_BYTES>>>(xh, wtq, b_qkv, qkv);
    }
    // 2) Causal attention (fp16 mma + ldmatrix + f16x2 exp)
    {
        dim3 grid(SEQ / 128, BATCH * NHEAD);    // (16, 64)
        attn_f16_kernel<<<grid, 256, ATT_SMEM_BYTES>>>(qkv, att);
    }
    // 3) Output projection (fp16 mma), fp32 output
    {
        dim3 grid(DMODEL / GBN, MTOT / GBM);    // (4, 64)
        gemm_f16_wide<<<grid, 256, GSMEM_BYTES>>>(att, wto, b_out, out, DMODEL);
    }
}

// round 10
// speedup vs baseline: 2.0081x; 1.0880x over previous
#include <cuda_runtime.h>
#include <cuda_fp16.h>
#include <math.h>
#include <stdint.h>

// Problem constants
#define BATCH   4
#define SEQ     2048
#define DMODEL  1024
#define NHEAD   16
#define DH      64
#define MTOT    (BATCH * SEQ)       // 8192
#define QKV_N   (3 * DMODEL)        // 3072
#define KDIM    DMODEL

// ---------------------------------------------------------------------------
// Scratch (device globals: allocation-free rule)
// ---------------------------------------------------------------------------
__device__ __half g_qkv[(size_t)MTOT * QKV_N];     // [8192,3072] fp16
__device__ __half g_att[(size_t)MTOT * DMODEL];    // [8192,1024] fp16
__device__ __half g_xh[(size_t)MTOT * DMODEL];     // x -> fp16
__device__ __half g_wtq[(size_t)QKV_N * DMODEL];   // W_qkv^T fp16
__device__ __half g_wto[(size_t)DMODEL * DMODEL];  // W_out^T fp16

// ---------------------------------------------------------------------------
// Helpers (portable sm_80+ PTX only)
// ---------------------------------------------------------------------------
__device__ __forceinline__ uint32_t smem_u32(const void* p) {
    uint32_t a;
    asm("{ .reg .u64 t; cvta.to.shared.u64 t, %1; cvt.u32.u64 %0, t; }" : "=r"(a) : "l"(p));
    return a;
}
__device__ __forceinline__ void cp16(uint32_t dst, const void* src) {
    asm volatile("cp.async.cg.shared.global [%0], [%1], 16;" :: "r"(dst), "l"(src));
}
#define CP_COMMIT()  asm volatile("cp.async.commit_group;" ::: "memory")
#define CP_WAIT1()   asm volatile("cp.async.wait_group 1;" ::: "memory")
#define CP_WAIT0()   asm volatile("cp.async.wait_group 0;" ::: "memory")

__device__ __forceinline__ void mma_f16(float* d, const uint32_t* a, const uint32_t* b) {
    asm volatile(
        "mma.sync.aligned.m16n8k16.row.col.f32.f16.f16.f32 "
        "{%0,%1,%2,%3}, {%4,%5,%6,%7}, {%8,%9}, {%0,%1,%2,%3};"
        : "+f"(d[0]), "+f"(d[1]), "+f"(d[2]), "+f"(d[3])
        : "r"(a[0]), "r"(a[1]), "r"(a[2]), "r"(a[3]), "r"(b[0]), "r"(b[1]));
}
__device__ __forceinline__ uint32_t ldu32(const __half* p) {
    return *(const uint32_t*)p;
}
__device__ __forceinline__ void ldsm_x4(uint32_t& r0, uint32_t& r1,
                                        uint32_t& r2, uint32_t& r3, uint32_t addr) {
    asm volatile("ldmatrix.sync.aligned.m8n8.x4.shared.b16 {%0,%1,%2,%3}, [%4];"
                 : "=r"(r0), "=r"(r1), "=r"(r2), "=r"(r3) : "r"(addr));
}
__device__ __forceinline__ void ldsm_x4_trans(uint32_t& r0, uint32_t& r1,
                                              uint32_t& r2, uint32_t& r3, uint32_t addr) {
    asm volatile("ldmatrix.sync.aligned.m8n8.x4.trans.shared.b16 {%0,%1,%2,%3}, [%4];"
                 : "=r"(r0), "=r"(r1), "=r"(r2), "=r"(r3) : "r"(addr));
}
__device__ __forceinline__ uint32_t exp2_f16x2(float lo, float hi) {
    uint32_t h, p;
    asm("cvt.rn.f16x2.f32 %0, %1, %2;" : "=r"(h) : "f"(hi), "f"(lo));
    asm("ex2.approx.f16x2 %0, %1;" : "=r"(p) : "r"(h));
    return p;
}
__device__ __forceinline__ float exp2_f32(float x) {
    float r;
    asm("ex2.approx.f32 %0, %1;" : "=f"(r) : "f"(x));
    return r;
}

// Per-lane ldmatrix relative offsets (in halves), for pitch P (halves):
// A-style (a0=row g,k2t | a1=row+8 | a2=col+8 | a3=row+8,col+8):
//   arel = ((lane>>3 & 1)*8 + (lane&7))*P + (lane>>4 & 1)*8
// B-style (r0=b0(n2) | r1=b1(n2) | r2=b0(n2+8) | r3=b1(n2+8)):
//   brel = ((lane>>4 & 1)*8 + (lane&7))*P + (lane>>3 & 1)*8
__device__ __forceinline__ uint32_t arel_of(int lane, int P) {
    return (uint32_t)((((lane >> 3) & 1) * 8 + (lane & 7)) * P + ((lane >> 4) & 1) * 8);
}
__device__ __forceinline__ uint32_t brel_of(int lane, int P) {
    return (uint32_t)((((lane >> 4) & 1) * 8 + (lane & 7)) * P + ((lane >> 3) & 1) * 8);
}

// ---------------------------------------------------------------------------
// GEMM1: fp16, 384 threads (12 warps, 2x6), tile 128x384, warp 64x64, BK=64.
// Fragment loads via ldmatrix.x4. 3-stage cp.async. Output __half.
// ---------------------------------------------------------------------------
#define PH 72
#define G1_M 128
#define G1_N 384
#define G1A_HALVES (G1_M * PH)
#define G1B_HALVES (G1_N * PH)
#define G1STAGE    (G1A_HALVES + G1B_HALVES)
#define G1SMEM_BYTES (3 * G1STAGE * 2)
#define NCHUNK (KDIM / 64)

__global__ __launch_bounds__(384, 1)
void gemm_f16_384(const __half* __restrict__ A, const __half* __restrict__ Bt,
                  const float* __restrict__ bias, __half* __restrict__ C)
{
    extern __shared__ __align__(16) __half smh[];

    const int tid = threadIdx.x;
    const int wid = tid >> 5;
    const int lane = tid & 31;
    const int g = lane >> 2;
    const int t = lane & 3;
    const int wm = wid / 6;
    const int wn = wid % 6;

    const int m0 = blockIdx.y * G1_M;
    const int n0 = blockIdx.x * G1_N;

    const __half* Abase = A  + (size_t)m0 * KDIM;
    const __half* Bbase = Bt + (size_t)n0 * KDIM;
    const uint32_t smu = smem_u32(smh);

    const uint32_t arel = arel_of(lane, PH) * 2u;
    const uint32_t brel = brel_of(lane, PH) * 2u;
    // warp-constant parts of fragment addresses (within a stage)
    const uint32_t awoff = (uint32_t)(wm * 64 * PH) * 2u + arel;
    const uint32_t bwoff = (uint32_t)(G1A_HALVES + wn * 64 * PH) * 2u + brel;

    auto load_chunk = [&](int c, int st) {
        const int k0 = c * 64;
        const uint32_t sa = smu + (uint32_t)(st * G1STAGE) * 2u;
        const uint32_t sb = sa + (uint32_t)G1A_HALVES * 2u;
#pragma unroll
        for (int i = 0; i < 3; ++i) {
            const int e = tid + 384 * i;
            if (e < 1024) {
                const int r = e >> 3, q = e & 7;
                cp16(sa + (uint32_t)(r * PH + q * 8) * 2u,
                     Abase + (size_t)r * KDIM + k0 + q * 8);
            }
        }
#pragma unroll
        for (int i = 0; i < 8; ++i) {
            const int e = tid + 384 * i;
            const int r = e >> 3, q = e & 7;
            cp16(sb + (uint32_t)(r * PH + q * 8) * 2u,
                 Bbase + (size_t)r * KDIM + k0 + q * 8);
        }
        CP_COMMIT();
    };

    float acc[4][8][4];
#pragma unroll
    for (int i = 0; i < 4; ++i)
#pragma unroll
        for (int j = 0; j < 8; ++j)
#pragma unroll
            for (int r = 0; r < 4; ++r) acc[i][j][r] = 0.f;

    load_chunk(0, 0);
    load_chunk(1, 1);

    for (int c = 0; c < NCHUNK; ++c) {
        const int s = c % 3;
        if (c + 1 < NCHUNK) CP_WAIT1(); else CP_WAIT0();
        __syncthreads();

        const uint32_t stg = smu + (uint32_t)(s * G1STAGE) * 2u;
        const uint32_t aB = stg + awoff;
        const uint32_t bB = stg + bwoff;

#pragma unroll
        for (int ks = 0; ks < 4; ++ks) {
            const uint32_t ko = (uint32_t)(ks * 16) * 2u;
            uint32_t af[4][4], bf[8][2];
#pragma unroll
            for (int mt = 0; mt < 4; ++mt)
                ldsm_x4(af[mt][0], af[mt][1], af[mt][2], af[mt][3],
                        aB + (uint32_t)(mt * 16 * PH) * 2u + ko);
#pragma unroll
            for (int np = 0; np < 4; ++np)
                ldsm_x4(bf[2 * np][0], bf[2 * np][1], bf[2 * np + 1][0], bf[2 * np + 1][1],
                        bB + (uint32_t)(np * 16 * PH) * 2u + ko);
#pragma unroll
            for (int mt = 0; mt < 4; ++mt)
#pragma unroll
                for (int nt = 0; nt < 8; ++nt)
                    mma_f16(acc[mt][nt], af[mt], bf[nt]);
        }

        if (c + 2 < NCHUNK) load_chunk(c + 2, (c + 2) % 3);
    }

#pragma unroll
    for (int mt = 0; mt < 4; ++mt) {
        const int row = m0 + wm * 64 + mt * 16 + g;
#pragma unroll
        for (int nt = 0; nt < 8; ++nt) {
            const int col = n0 + wn * 64 + nt * 8 + t * 2;
            const float bx = __ldg(bias + col), by = __ldg(bias + col + 1);
            *(__half2*)(C + (size_t)row * QKV_N + col) =
                __floats2half2_rn(acc[mt][nt][0] + bx, acc[mt][nt][1] + by);
            *(__half2*)(C + (size_t)(row + 8) * QKV_N + col) =
                __floats2half2_rn(acc[mt][nt][2] + bx, acc[mt][nt][3] + by);
        }
    }
}

// ---------------------------------------------------------------------------
// GEMM3: fp16, 256 threads, tile 128x256, warp 64x64, ldmatrix frags, f32 out.
// ---------------------------------------------------------------------------
#define GBM 128
#define GBN 256
#define GA_HALVES (GBM * PH)
#define GB_HALVES (GBN * PH)
#define GSTAGE    (GA_HALVES + GB_HALVES)
#define GSMEM_BYTES (3 * GSTAGE * 2)

__global__ __launch_bounds__(256, 1)
void gemm_f16_wide(const __half* __restrict__ A, const __half* __restrict__ Bt,
                   const float* __restrict__ bias, float* __restrict__ C, int Ntot)
{
    extern __shared__ __align__(16) __half smh[];

    const int tid = threadIdx.x;
    const int wid = tid >> 5;
    const int lane = tid & 31;
    const int g = lane >> 2;
    const int t = lane & 3;
    const int wm = wid >> 2;
    const int wn = wid & 3;

    const int m0 = blockIdx.y * GBM;
    const int n0 = blockIdx.x * GBN;

    const __half* Abase = A  + (size_t)m0 * KDIM;
    const __half* Bbase = Bt + (size_t)n0 * KDIM;
    const uint32_t smu = smem_u32(smh);

    const uint32_t arel = arel_of(lane, PH) * 2u;
    const uint32_t brel = brel_of(lane, PH) * 2u;
    const uint32_t awoff = (uint32_t)(wm * 64 * PH) * 2u + arel;
    const uint32_t bwoff = (uint32_t)(GA_HALVES + wn * 64 * PH) * 2u + brel;

    auto load_chunk = [&](int c, int st) {
        const int k0 = c * 64;
        const uint32_t sa = smu + (uint32_t)(st * GSTAGE) * 2u;
        const uint32_t sb = sa + (uint32_t)GA_HALVES * 2u;
#pragma unroll
        for (int i = 0; i < 4; ++i) {
            const int e = tid + 256 * i;
            const int r = e >> 3, q = e & 7;
            cp16(sa + (uint32_t)(r * PH + q * 8) * 2u, Abase + (size_t)r * KDIM + k0 + q * 8);
        }
#pragma unroll
        for (int i = 0; i < 8; ++i) {
            const int e = tid + 256 * i;
            const int r = e >> 3, q = e & 7;
            cp16(sb + (uint32_t)(r * PH + q * 8) * 2u, Bbase + (size_t)r * KDIM + k0 + q * 8);
        }
        CP_COMMIT();
    };

    float acc[4][8][4];
#pragma unroll
    for (int i = 0; i < 4; ++i)
#pragma unroll
        for (int j = 0; j < 8; ++j)
#pragma unroll
            for (int r = 0; r < 4; ++r) acc[i][j][r] = 0.f;

    load_chunk(0, 0);
    load_chunk(1, 1);

    for (int c = 0; c < NCHUNK; ++c) {
        const int s = c % 3;
        if (c + 1 < NCHUNK) CP_WAIT1(); else CP_WAIT0();
        __syncthreads();

        const uint32_t stg = smu + (uint32_t)(s * GSTAGE) * 2u;
        const uint32_t aB = stg + awoff;
        const uint32_t bB = stg + bwoff;

#pragma unroll
        for (int ks = 0; ks < 4; ++ks) {
            const uint32_t ko = (uint32_t)(ks * 16) * 2u;
            uint32_t af[4][4], bf[8][2];
#pragma unroll
            for (int mt = 0; mt < 4; ++mt)
                ldsm_x4(af[mt][0], af[mt][1], af[mt][2], af[mt][3],
                        aB + (uint32_t)(mt * 16 * PH) * 2u + ko);
#pragma unroll
            for (int np = 0; np < 4; ++np)
                ldsm_x4(bf[2 * np][0], bf[2 * np][1], bf[2 * np + 1][0], bf[2 * np + 1][1],
                        bB + (uint32_t)(np * 16 * PH) * 2u + ko);
#pragma unroll
            for (int mt = 0; mt < 4; ++mt)
#pragma unroll
                for (int nt = 0; nt < 8; ++nt)
                    mma_f16(acc[mt][nt], af[mt], bf[nt]);
        }

        if (c + 2 < NCHUNK) load_chunk(c + 2, (c + 2) % 3);
    }

#pragma unroll
    for (int mt = 0; mt < 4; ++mt) {
        const int row = m0 + wm * 64 + mt * 16 + g;
#pragma unroll
        for (int nt = 0; nt < 8; ++nt) {
            const int col = n0 + wn * 64 + nt * 8 + t * 2;
            const float bx = __ldg(bias + col), by = __ldg(bias + col + 1);
            float2 lo = { acc[mt][nt][0] + bx, acc[mt][nt][1] + by };
            float2 hi = { acc[mt][nt][2] + bx, acc[mt][nt][3] + by };
            *(float2*)(C + (size_t)row * Ntot + col)       = lo;
            *(float2*)(C + (size_t)(row + 8) * Ntot + col) = hi;
        }
    }
}

// ---------------------------------------------------------------------------
// Preconditioning kernels
// ---------------------------------------------------------------------------
__global__ __launch_bounds__(256)
void cvt_x_kernel(const float* __restrict__ x, __half* __restrict__ xh, int n4)
{
    int i = blockIdx.x * blockDim.x + threadIdx.x;
    if (i < n4) {
        float4 v = ((const float4*)x)[i];
        __half2 lo = __floats2half2_rn(v.x, v.y);
        __half2 hi = __floats2half2_rn(v.z, v.w);
        uint2 o = { *(uint32_t*)&lo, *(uint32_t*)&hi };
        ((uint2*)xh)[i] = o;
    }
}

__global__ __launch_bounds__(256)
void transpose_half_kernel(const float* __restrict__ W, __half* __restrict__ Wt, int N)
{
    __shared__ float tbuf[32][33];
    const int nb = blockIdx.x * 32, kb = blockIdx.y * 32;
    const int tx = threadIdx.x, ty = threadIdx.y;
#pragma unroll
    for (int i = 0; i < 32; i += 8)
        tbuf[ty + i][tx] = W[(size_t)(kb + ty + i) * N + nb + tx];
    __syncthreads();
#pragma unroll
    for (int i = 0; i < 32; i += 8)
        Wt[(size_t)(nb + ty + i) * KDIM + kb + tx] = __float2half_rn(tbuf[tx][ty + i]);
}

// ---------------------------------------------------------------------------
// fp16 causal flash attention: hoisted Q fragments, ldmatrix K and V frags,
// ex2.f16x2 softmax. CTA: one (b,h) x 128 q rows, 8 warps x 16 rows.
// ---------------------------------------------------------------------------
#define AP 72
#define OFF_K  9216
#define OFF_V  13824
#define OFF_P  18432
#define ATT_SMEM_HALVES 27648
#define ATT_SMEM_BYTES  (ATT_SMEM_HALVES * 2)

__global__ __launch_bounds__(256, 2)
void attn_f16_kernel(const __half* __restrict__ qkv, __half* __restrict__ out)
{
    extern __shared__ __align__(16) __half smh[];
    const uint32_t smu = smem_u32(smh);

    const int tid = threadIdx.x;
    const int wid = tid >> 5;
    const int lane = tid & 31;
    const int g = lane >> 2, t = lane & 3;

    const int qt = gridDim.x - 1 - blockIdx.x;   // heavy tiles first
    const int q0 = qt * 128;
    const int bh = blockIdx.y;
    const int b = bh >> 4, h = bh & 15;

    const __half* base = qkv + (size_t)b * SEQ * QKV_N;

#pragma unroll
    for (int i = 0; i < 4; ++i) {
        const int e = tid + 256 * i;
        const int r = e >> 3, q = e & 7;
        cp16(smu + (uint32_t)(r * AP + q * 8) * 2u,
             base + (size_t)(q0 + r) * QKV_N + h * DH + q * 8);
    }
    auto load_kv = [&](int k0) {
#pragma unroll
        for (int i = 0; i < 2; ++i) {
            const int e = tid + 256 * i;
            const int r = e >> 3, q = e & 7;
            const __half* krow = base + (size_t)(k0 + r) * QKV_N + DMODEL + h * DH + q * 8;
            const __half* vrow = base + (size_t)(k0 + r) * QKV_N + 2 * DMODEL + h * DH + q * 8;
            cp16(smu + (uint32_t)(OFF_K + r * AP + q * 8) * 2u, krow);
            cp16(smu + (uint32_t)(OFF_V + r * AP + q * 8) * 2u, vrow);
        }
    };
    load_kv(0);
    CP_COMMIT(); CP_WAIT0();
    __syncthreads();

    const int niter = 2 * (qt + 1);
    const int row0 = wid * 16 + g;
    const int qrow0 = q0 + row0;
    const int qrow1 = qrow0 + 8;
    const float l2s = 0.1803368801111204f;   // (1/8) * log2(e)

    // ldmatrix bases
    const uint32_t arel = arel_of(lane, AP) * 2u;
    const uint32_t krel = brel_of(lane, AP) * 2u;
    const uint32_t qbase = smu + (uint32_t)(wid * 16 * AP) * 2u + arel;
    const uint32_t kbase = smu + (uint32_t)(OFF_K) * 2u + krel;
    const uint32_t vbase = smu +
        (uint32_t)((OFF_V + (lane & 15) * AP + ((lane >> 4) << 3)) * 2);

    // ---- hoist Q fragments (loop-invariant) ----
    uint32_t qf[4][4];
#pragma unroll
    for (int kd = 0; kd < 4; ++kd)
        ldsm_x4(qf[kd][0], qf[kd][1], qf[kd][2], qf[kd][3],
                qbase + (uint32_t)(kd * 16) * 2u);

    float m0 = -INFINITY, m1 = -INFINITY, l0 = 0.f, l1 = 0.f;
    float accO[8][4];
#pragma unroll
    for (int nt = 0; nt < 8; ++nt)
#pragma unroll
        for (int r = 0; r < 4; ++r) accO[nt][r] = 0.f;

    __half* Ps = smh + OFF_P;

    for (int it = 0; it < niter; ++it) {
        const int k0 = it * 64;

        // ---- S = Q K^T (K B-fragments via ldmatrix.x4) ----
        float accS[8][4];
#pragma unroll
        for (int nt = 0; nt < 8; ++nt)
#pragma unroll
            for (int r = 0; r < 4; ++r) accS[nt][r] = 0.f;

#pragma unroll
        for (int kd = 0; kd < 4; ++kd) {
            const uint32_t ko = (uint32_t)(kd * 16) * 2u;
#pragma unroll
            for (int np = 0; np < 4; ++np) {
                uint32_t b0, b1, b2, b3;
                ldsm_x4(b0, b1, b2, b3, kbase + (uint32_t)(np * 16 * AP) * 2u + ko);
                uint32_t bf0[2] = { b0, b1 };
                uint32_t bf1[2] = { b2, b3 };
                mma_f16(accS[2 * np],     qf[kd], bf0);
                mma_f16(accS[2 * np + 1], qf[kd], bf1);
            }
        }

        // ---- mask + online softmax (log2 domain) ----
        float pm0 = -INFINITY, pm1 = -INFINITY;
#pragma unroll
        for (int nt = 0; nt < 8; ++nt) {
            const int key = k0 + nt * 8 + 2 * t;
            accS[nt][0] = (key     <= qrow0) ? accS[nt][0] * l2s : -INFINITY;
            accS[nt][1] = (key + 1 <= qrow0) ? accS[nt][1] * l2s : -INFINITY;
            accS[nt][2] = (key     <= qrow1) ? accS[nt][2] * l2s : -INFINITY;
            accS[nt][3] = (key + 1 <= qrow1) ? accS[nt][3] * l2s : -INFINITY;
            pm0 = fmaxf(pm0, fmaxf(accS[nt][0], accS[nt][1]));
            pm1 = fmaxf(pm1, fmaxf(accS[nt][2], accS[nt][3]));
        }
        pm0 = fmaxf(pm0, __shfl_xor_sync(0xffffffffu, pm0, 1));
        pm0 = fmaxf(pm0, __shfl_xor_sync(0xffffffffu, pm0, 2));
        pm1 = fmaxf(pm1, __shfl_xor_sync(0xffffffffu, pm1, 1));
        pm1 = fmaxf(pm1, __shfl_xor_sync(0xffffffffu, pm1, 2));

        const float mn0 = fmaxf(m0, pm0), mn1 = fmaxf(m1, pm1);
        const float c0 = exp2_f32(m0 - mn0), c1 = exp2_f32(m1 - mn1);
        float ls0 = 0.f, ls1 = 0.f;
#pragma unroll
        for (int nt = 0; nt < 8; ++nt) {
            const uint32_t p01 = exp2_f16x2(accS[nt][0] - mn0, accS[nt][1] - mn0);
            const uint32_t p23 = exp2_f16x2(accS[nt][2] - mn1, accS[nt][3] - mn1);
            *(uint32_t*)(Ps + (row0)     * AP + nt * 8 + 2 * t) = p01;
            *(uint32_t*)(Ps + (row0 + 8) * AP + nt * 8 + 2 * t) = p23;
            const float2 f01 = __half22float2(*(const __half2*)&p01);
            const float2 f23 = __half22float2(*(const __half2*)&p23);
            ls0 += f01.x + f01.y;
            ls1 += f23.x + f23.y;
        }
        ls0 += __shfl_xor_sync(0xffffffffu, ls0, 1);
        ls0 += __shfl_xor_sync(0xffffffffu, ls0, 2);
        ls1 += __shfl_xor_sync(0xffffffffu, ls1, 1);
        ls1 += __shfl_xor_sync(0xffffffffu, ls1, 2);
        l0 = l0 * c0 + ls0;
        l1 = l1 * c1 + ls1;
        m0 = mn0; m1 = mn1;
#pragma unroll
        for (int nt = 0; nt < 8; ++nt) {
            accO[nt][0] *= c0; accO[nt][1] *= c0;
            accO[nt][2] *= c1; accO[nt][3] *= c1;
        }
        __syncwarp();   // P tile is warp-private

        // ---- O += P V  (V via ldmatrix.x4.trans) ----
#pragma unroll
        for (int kc = 0; kc < 4; ++kc) {
            const int koff = kc * 16;
            uint32_t a[4];
            a[0] = ldu32(Ps + (row0)     * AP + koff + 2 * t);
            a[1] = ldu32(Ps + (row0 + 8) * AP + koff + 2 * t);
            a[2] = ldu32(Ps + (row0)     * AP + koff + 2 * t + 8);
            a[3] = ldu32(Ps + (row0 + 8) * AP + koff + 2 * t + 8);
#pragma unroll
            for (int ntp = 0; ntp < 4; ++ntp) {
                uint32_t b0, b1, b2, b3;
                ldsm_x4_trans(b0, b1, b2, b3,
                              vbase + (uint32_t)((koff * AP + ntp * 16) * 2));
                uint32_t bf0[2] = { b0, b1 };
                uint32_t bf1[2] = { b2, b3 };
                mma_f16(accO[2 * ntp],     a, bf0);
                mma_f16(accO[2 * ntp + 1], a, bf1);
            }
        }

        if (it + 1 < niter) {
            __syncthreads();
            load_kv(k0 + 64);
            CP_COMMIT(); CP_WAIT0();
            __syncthreads();
        }
    }

    // ---- normalize + write fp16 ----
    const float rl0 = 1.0f / l0, rl1 = 1.0f / l1;
    __half* o0 = out + (size_t)(b * SEQ + qrow0) * DMODEL + h * DH;
    __half* o1 = out + (size_t)(b * SEQ + qrow1) * DMODEL + h * DH;
#pragma unroll
    for (int nt = 0; nt < 8; ++nt) {
        const int col = nt * 8 + 2 * t;
        *(__half2*)(o0 + col) = __floats2half2_rn(accO[nt][0] * rl0, accO[nt][1] * rl0);
        *(__half2*)(o1 + col) = __floats2half2_rn(accO[nt][2] * rl1, accO[nt][3] * rl1);
    }
}

// ---------------------------------------------------------------------------
// kernel_launch
// ---------------------------------------------------------------------------
extern "C" void kernel_launch(void* const* d_in, const int* in_sizes, int n_in,
                              void* d_out, int out_size)
{
    const float* x     = (const float*)d_in[0];
    const float* W_qkv = (const float*)d_in[1];
    const float* b_qkv = (const float*)d_in[2];
    const float* W_out = (const float*)d_in[3];
    const float* b_out = (const float*)d_in[4];
    float* out = (float*)d_out;

    __half* qkv; cudaGetSymbolAddress((void**)&qkv, g_qkv);
    __half* att; cudaGetSymbolAddress((void**)&att, g_att);
    __half* xh;  cudaGetSymbolAddress((void**)&xh,  g_xh);
    __half* wtq; cudaGetSymbolAddress((void**)&wtq, g_wtq);
    __half* wto; cudaGetSymbolAddress((void**)&wto, g_wto);

    cudaFuncSetAttribute(gemm_f16_384,
                         cudaFuncAttributeMaxDynamicSharedMemorySize, G1SMEM_BYTES);
    cudaFuncSetAttribute(gemm_f16_wide,
                         cudaFuncAttributeMaxDynamicSharedMemorySize, GSMEM_BYTES);
    cudaFuncSetAttribute(attn_f16_kernel,
                         cudaFuncAttributeMaxDynamicSharedMemorySize, ATT_SMEM_BYTES);

    // 0) precondition inputs to fp16
    {
        int n4 = MTOT * DMODEL / 4;
        cvt_x_kernel<<<(n4 + 255) / 256, 256>>>(x, xh, n4);
        transpose_half_kernel<<<dim3(QKV_N / 32, KDIM / 32), dim3(32, 8)>>>(W_qkv, wtq, QKV_N);
        transpose_half_kernel<<<dim3(DMODEL / 32, KDIM / 32), dim3(32, 8)>>>(W_out, wto, DMODEL);
    }
    // 1) QKV projection
    {
        dim3 grid(QKV_N / G1_N, MTOT / G1_M);   // (8, 64)
        gemm_f16_384<<<grid, 384, G1SMEM_BYTES>>>(xh, wtq, b_qkv, qkv);
    }
    // 2) Causal attention
    {
        dim3 grid(SEQ / 128, BATCH * NHEAD);    // (16, 64)
        attn_f16_kernel<<<grid, 256, ATT_SMEM_BYTES>>>(qkv, att);
    }
    // 3) Output projection
    {
        dim3 grid(DMODEL / GBN, MTOT / GBM);    // (4, 64)
        gemm_f16_wide<<<grid, 256, GSMEM_BYTES>>>(att, wto, b_out, out, DMODEL);
    }
}

// round 12
// speedup vs baseline: 2.0284x; 1.0101x over previous
#include <cuda_runtime.h>
#include <cuda_fp16.h>
#include <math.h>
#include <stdint.h>

// Problem constants
#define BATCH   4
#define SEQ     2048
#define DMODEL  1024
#define NHEAD   16
#define DH      64
#define MTOT    (BATCH * SEQ)       // 8192
#define QKV_N   (3 * DMODEL)        // 3072
#define KDIM    DMODEL

// ---------------------------------------------------------------------------
// Scratch (device globals: allocation-free rule)
// ---------------------------------------------------------------------------
__device__ __half g_qkv[(size_t)MTOT * QKV_N];     // [8192,3072] fp16
__device__ __half g_att[(size_t)MTOT * DMODEL];    // [8192,1024] fp16
__device__ __half g_xh[(size_t)MTOT * DMODEL];     // x -> fp16
__device__ __half g_wtq[(size_t)QKV_N * DMODEL];   // W_qkv^T fp16
__device__ __half g_wto[(size_t)DMODEL * DMODEL];  // W_out^T fp16

// ---------------------------------------------------------------------------
// Helpers (portable sm_80+ PTX only)
// ---------------------------------------------------------------------------
__device__ __forceinline__ uint32_t smem_u32(const void* p) {
    uint32_t a;
    asm("{ .reg .u64 t; cvta.to.shared.u64 t, %1; cvt.u32.u64 %0, t; }" : "=r"(a) : "l"(p));
    return a;
}
__device__ __forceinline__ void cp16(uint32_t dst, const void* src) {
    asm volatile("cp.async.cg.shared.global [%0], [%1], 16;" :: "r"(dst), "l"(src));
}
#define CP_COMMIT()  asm volatile("cp.async.commit_group;" ::: "memory")
#define CP_WAIT1()   asm volatile("cp.async.wait_group 1;" ::: "memory")
#define CP_WAIT0()   asm volatile("cp.async.wait_group 0;" ::: "memory")

__device__ __forceinline__ void mma_f16(float* d, const uint32_t* a, const uint32_t* b) {
    asm volatile(
        "mma.sync.aligned.m16n8k16.row.col.f32.f16.f16.f32 "
        "{%0,%1,%2,%3}, {%4,%5,%6,%7}, {%8,%9}, {%0,%1,%2,%3};"
        : "+f"(d[0]), "+f"(d[1]), "+f"(d[2]), "+f"(d[3])
        : "r"(a[0]), "r"(a[1]), "r"(a[2]), "r"(a[3]), "r"(b[0]), "r"(b[1]));
}
__device__ __forceinline__ uint32_t ldu32(const __half* p) {
    return *(const uint32_t*)p;
}
__device__ __forceinline__ void ldsm_x4(uint32_t& r0, uint32_t& r1,
                                        uint32_t& r2, uint32_t& r3, uint32_t addr) {
    asm volatile("ldmatrix.sync.aligned.m8n8.x4.shared.b16 {%0,%1,%2,%3}, [%4];"
                 : "=r"(r0), "=r"(r1), "=r"(r2), "=r"(r3) : "r"(addr));
}
__device__ __forceinline__ void ldsm_x4_trans(uint32_t& r0, uint32_t& r1,
                                              uint32_t& r2, uint32_t& r3, uint32_t addr) {
    asm volatile("ldmatrix.sync.aligned.m8n8.x4.trans.shared.b16 {%0,%1,%2,%3}, [%4];"
                 : "=r"(r0), "=r"(r1), "=r"(r2), "=r"(r3) : "r"(addr));
}
__device__ __forceinline__ uint32_t exp2_f16x2(float lo, float hi) {
    uint32_t h, p;
    asm("cvt.rn.f16x2.f32 %0, %1, %2;" : "=r"(h) : "f"(hi), "f"(lo));
    asm("ex2.approx.f16x2 %0, %1;" : "=r"(p) : "r"(h));
    return p;
}
__device__ __forceinline__ float exp2_f32(float x) {
    float r;
    asm("ex2.approx.f32 %0, %1;" : "=f"(r) : "f"(x));
    return r;
}

// Per-lane ldmatrix relative offsets (in halves), pitch P (halves)
__device__ __forceinline__ uint32_t arel_of(int lane, int P) {
    return (uint32_t)((((lane >> 3) & 1) * 8 + (lane & 7)) * P + ((lane >> 4) & 1) * 8);
}
__device__ __forceinline__ uint32_t brel_of(int lane, int P) {
    return (uint32_t)((((lane >> 4) & 1) * 8 + (lane & 7)) * P + ((lane >> 3) & 1) * 8);
}

// ---------------------------------------------------------------------------
// Unified fp16 GEMM: C[M,Ntot] = A[M,1024] @ Bt[Ntot,1024]^T + bias
// 512 threads = 16 warps (4m x 4n), CTA tile 128x256, warp tile 32x64, BK=64.
// ldmatrix fragments, 3-stage cp.async.
// ---------------------------------------------------------------------------
#define PH 72
#define GBM 128
#define GBN 256
#define GA_HALVES (GBM * PH)                 // 9216
#define GB_HALVES (GBN * PH)                 // 18432
#define GSTAGE    (GA_HALVES + GB_HALVES)    // 27648 halves
#define GSMEM_BYTES (3 * GSTAGE * 2)         // 165888 B
#define NCHUNK (KDIM / 64)                   // 16

template <int OUT_HALF>
__global__ __launch_bounds__(512, 1)
void gemm_f16_512(const __half* __restrict__ A, const __half* __restrict__ Bt,
                  const float* __restrict__ bias, void* __restrict__ Cv, int Ntot)
{
    extern __shared__ __align__(16) __half smh[];

    const int tid = threadIdx.x;
    const int wid = tid >> 5;
    const int lane = tid & 31;
    const int g = lane >> 2;
    const int t = lane & 3;
    const int wm = wid >> 2;      // 0..3 -> 32 rows
    const int wn = wid & 3;       // 0..3 -> 64 cols

    const int m0 = blockIdx.y * GBM;
    const int n0 = blockIdx.x * GBN;

    const __half* Abase = A  + (size_t)m0 * KDIM;
    const __half* Bbase = Bt + (size_t)n0 * KDIM;
    const uint32_t smu = smem_u32(smh);

    const uint32_t awoff = (uint32_t)(wm * 32 * PH) * 2u + arel_of(lane, PH) * 2u;
    const uint32_t bwoff = (uint32_t)(GA_HALVES + wn * 64 * PH) * 2u + brel_of(lane, PH) * 2u;

    auto load_chunk = [&](int c, int st) {
        const int k0 = c * 64;
        const uint32_t sa = smu + (uint32_t)(st * GSTAGE) * 2u;
        const uint32_t sb = sa + (uint32_t)GA_HALVES * 2u;
#pragma unroll
        for (int i = 0; i < 2; ++i) {
            const int e = tid + 512 * i;            // 0..1023
            const int r = e >> 3, q = e & 7;
            cp16(sa + (uint32_t)(r * PH + q * 8) * 2u, Abase + (size_t)r * KDIM + k0 + q * 8);
        }
#pragma unroll
        for (int i = 0; i < 4; ++i) {
            const int e = tid + 512 * i;            // 0..2047
            const int r = e >> 3, q = e & 7;
            cp16(sb + (uint32_t)(r * PH + q * 8) * 2u, Bbase + (size_t)r * KDIM + k0 + q * 8);
        }
        CP_COMMIT();
    };

    float acc[2][8][4];
#pragma unroll
    for (int i = 0; i < 2; ++i)
#pragma unroll
        for (int j = 0; j < 8; ++j)
#pragma unroll
            for (int r = 0; r < 4; ++r) acc[i][j][r] = 0.f;

    load_chunk(0, 0);
    load_chunk(1, 1);

    for (int c = 0; c < NCHUNK; ++c) {
        const int s = c % 3;
        if (c + 1 < NCHUNK) CP_WAIT1(); else CP_WAIT0();
        __syncthreads();

        const uint32_t stg = smu + (uint32_t)(s * GSTAGE) * 2u;
        const uint32_t aB = stg + awoff;
        const uint32_t bB = stg + bwoff;

#pragma unroll
        for (int ks = 0; ks < 4; ++ks) {
            const uint32_t ko = (uint32_t)(ks * 16) * 2u;
            uint32_t af[2][4], bf[8][2];
#pragma unroll
            for (int mt = 0; mt < 2; ++mt)
                ldsm_x4(af[mt][0], af[mt][1], af[mt][2], af[mt][3],
                        aB + (uint32_t)(mt * 16 * PH) * 2u + ko);
#pragma unroll
            for (int np = 0; np < 4; ++np)
                ldsm_x4(bf[2 * np][0], bf[2 * np][1], bf[2 * np + 1][0], bf[2 * np + 1][1],
                        bB + (uint32_t)(np * 16 * PH) * 2u + ko);
#pragma unroll
            for (int mt = 0; mt < 2; ++mt)
#pragma unroll
                for (int nt = 0; nt < 8; ++nt)
                    mma_f16(acc[mt][nt], af[mt], bf[nt]);
        }

        if (c + 2 < NCHUNK) load_chunk(c + 2, (c + 2) % 3);
    }

#pragma unroll
    for (int mt = 0; mt < 2; ++mt) {
        const int row = m0 + wm * 32 + mt * 16 + g;
#pragma unroll
        for (int nt = 0; nt < 8; ++nt) {
            const int col = n0 + wn * 64 + nt * 8 + t * 2;
            const float bx = __ldg(bias + col), by = __ldg(bias + col + 1);
            if (OUT_HALF) {
                __half* C = (__half*)Cv;
                *(__half2*)(C + (size_t)row * Ntot + col) =
                    __floats2half2_rn(acc[mt][nt][0] + bx, acc[mt][nt][1] + by);
                *(__half2*)(C + (size_t)(row + 8) * Ntot + col) =
                    __floats2half2_rn(acc[mt][nt][2] + bx, acc[mt][nt][3] + by);
            } else {
                float* C = (float*)Cv;
                float2 lo = { acc[mt][nt][0] + bx, acc[mt][nt][1] + by };
                float2 hi = { acc[mt][nt][2] + bx, acc[mt][nt][3] + by };
                *(float2*)(C + (size_t)row * Ntot + col)       = lo;
                *(float2*)(C + (size_t)(row + 8) * Ntot + col) = hi;
            }
        }
    }
}

// ---------------------------------------------------------------------------
// Merged preconditioning (FIXED coverage): one launch does x->fp16 (range A:
// 1024 blocks x 2048 float4 = 2M float4 = 8M floats), W_qkv^T (B), W_out^T (C).
// blockDim (32,8) = 256 threads.
// ---------------------------------------------------------------------------
#define NB_X   1024
#define NB_WQ  (96 * 32)
#define NB_WO  (32 * 32)
#define NB_TOT (NB_X + NB_WQ + NB_WO)

__global__ __launch_bounds__(256)
void precond_kernel(const float* __restrict__ x, __half* __restrict__ xh,
                    const float* __restrict__ Wq, __half* __restrict__ Wtq,
                    const float* __restrict__ Wo, __half* __restrict__ Wto)
{
    __shared__ float tbuf[32][33];
    const int bid = blockIdx.x;
    const int tx = threadIdx.x, ty = threadIdx.y;
    const int tid = ty * 32 + tx;

    if (bid < NB_X) {
        // x convert: 8 float4 per thread -> 2048 float4 per block
        const int base = bid * 2048 + tid;
#pragma unroll
        for (int i = 0; i < 8; ++i) {
            const int idx = base + 256 * i;   // covers 1024*2048 = 2M float4
            float4 v = ((const float4*)x)[idx];
            __half2 lo = __floats2half2_rn(v.x, v.y);
            __half2 hi = __floats2half2_rn(v.z, v.w);
            uint2 o = { *(uint32_t*)&lo, *(uint32_t*)&hi };
            ((uint2*)xh)[idx] = o;
        }
        return;
    }

    const float* W; __half* Wt; int N, tb;
    if (bid < NB_X + NB_WQ) { W = Wq; Wt = Wtq; N = QKV_N; tb = bid - NB_X; }
    else                    { W = Wo; Wt = Wto; N = DMODEL; tb = bid - NB_X - NB_WQ; }

    const int ntiles = N / 32;
    const int nb = (tb % ntiles) * 32;
    const int kb = (tb / ntiles) * 32;
#pragma unroll
    for (int i = 0; i < 32; i += 8)
        tbuf[ty + i][tx] = W[(size_t)(kb + ty + i) * N + nb + tx];
    __syncthreads();
#pragma unroll
    for (int i = 0; i < 32; i += 8)
        Wt[(size_t)(nb + ty + i) * KDIM + kb + tx] = __float2half_rn(tbuf[tx][ty + i]);
}

// ---------------------------------------------------------------------------
// fp16 causal flash attention (round-10 version, unchanged).
// ---------------------------------------------------------------------------
#define AP 72
#define OFF_K  9216
#define OFF_V  13824
#define OFF_P  18432
#define ATT_SMEM_HALVES 27648
#define ATT_SMEM_BYTES  (ATT_SMEM_HALVES * 2)

__global__ __launch_bounds__(256, 2)
void attn_f16_kernel(const __half* __restrict__ qkv, __half* __restrict__ out)
{
    extern __shared__ __align__(16) __half smh[];
    const uint32_t smu = smem_u32(smh);

    const int tid = threadIdx.x;
    const int wid = tid >> 5;
    const int lane = tid & 31;
    const int g = lane >> 2, t = lane & 3;

    const int qt = gridDim.x - 1 - blockIdx.x;
    const int q0 = qt * 128;
    const int bh = blockIdx.y;
    const int b = bh >> 4, h = bh & 15;

    const __half* base = qkv + (size_t)b * SEQ * QKV_N;

#pragma unroll
    for (int i = 0; i < 4; ++i) {
        const int e = tid + 256 * i;
        const int r = e >> 3, q = e & 7;
        cp16(smu + (uint32_t)(r * AP + q * 8) * 2u,
             base + (size_t)(q0 + r) * QKV_N + h * DH + q * 8);
    }
    auto load_kv = [&](int k0) {
#pragma unroll
        for (int i = 0; i < 2; ++i) {
            const int e = tid + 256 * i;
            const int r = e >> 3, q = e & 7;
            const __half* krow = base + (size_t)(k0 + r) * QKV_N + DMODEL + h * DH + q * 8;
            const __half* vrow = base + (size_t)(k0 + r) * QKV_N + 2 * DMODEL + h * DH + q * 8;
            cp16(smu + (uint32_t)(OFF_K + r * AP + q * 8) * 2u, krow);
            cp16(smu + (uint32_t)(OFF_V + r * AP + q * 8) * 2u, vrow);
        }
    };
    load_kv(0);
    CP_COMMIT(); CP_WAIT0();
    __syncthreads();

    const int niter = 2 * (qt + 1);
    const int row0 = wid * 16 + g;
    const int qrow0 = q0 + row0;
    const int qrow1 = qrow0 + 8;
    const float l2s = 0.1803368801111204f;   // (1/8) * log2(e)

    const uint32_t qbase = smu + (uint32_t)(wid * 16 * AP) * 2u + arel_of(lane, AP) * 2u;
    const uint32_t kbase = smu + (uint32_t)(OFF_K) * 2u + brel_of(lane, AP) * 2u;
    const uint32_t vbase = smu +
        (uint32_t)((OFF_V + (lane & 15) * AP + ((lane >> 4) << 3)) * 2);

    uint32_t qf[4][4];
#pragma unroll
    for (int kd = 0; kd < 4; ++kd)
        ldsm_x4(qf[kd][0], qf[kd][1], qf[kd][2], qf[kd][3],
                qbase + (uint32_t)(kd * 16) * 2u);

    float m0 = -INFINITY, m1 = -INFINITY, l0 = 0.f, l1 = 0.f;
    float accO[8][4];
#pragma unroll
    for (int nt = 0; nt < 8; ++nt)
#pragma unroll
        for (int r = 0; r < 4; ++r) accO[nt][r] = 0.f;

    __half* Ps = smh + OFF_P;

    for (int it = 0; it < niter; ++it) {
        const int k0 = it * 64;

        float accS[8][4];
#pragma unroll
        for (int nt = 0; nt < 8; ++nt)
#pragma unroll
            for (int r = 0; r < 4; ++r) accS[nt][r] = 0.f;

#pragma unroll
        for (int kd = 0; kd < 4; ++kd) {
            const uint32_t ko = (uint32_t)(kd * 16) * 2u;
#pragma unroll
            for (int np = 0; np < 4; ++np) {
                uint32_t b0, b1, b2, b3;
                ldsm_x4(b0, b1, b2, b3, kbase + (uint32_t)(np * 16 * AP) * 2u + ko);
                uint32_t bf0[2] = { b0, b1 };
                uint32_t bf1[2] = { b2, b3 };
                mma_f16(accS[2 * np],     qf[kd], bf0);
                mma_f16(accS[2 * np + 1], qf[kd], bf1);
            }
        }

        float pm0 = -INFINITY, pm1 = -INFINITY;
#pragma unroll
        for (int nt = 0; nt < 8; ++nt) {
            const int key = k0 + nt * 8 + 2 * t;
            accS[nt][0] = (key     <= qrow0) ? accS[nt][0] * l2s : -INFINITY;
            accS[nt][1] = (key + 1 <= qrow0) ? accS[nt][1] * l2s : -INFINITY;
            accS[nt][2] = (key     <= qrow1) ? accS[nt][2] * l2s : -INFINITY;
            accS[nt][3] = (key + 1 <= qrow1) ? accS[nt][3] * l2s : -INFINITY;
            pm0 = fmaxf(pm0, fmaxf(accS[nt][0], accS[nt][1]));
            pm1 = fmaxf(pm1, fmaxf(accS[nt][2], accS[nt][3]));
        }
        pm0 = fmaxf(pm0, __shfl_xor_sync(0xffffffffu, pm0, 1));
        pm0 = fmaxf(pm0, __shfl_xor_sync(0xffffffffu, pm0, 2));
        pm1 = fmaxf(pm1, __shfl_xor_sync(0xffffffffu, pm1, 1));
        pm1 = fmaxf(pm1, __shfl_xor_sync(0xffffffffu, pm1, 2));

        const float mn0 = fmaxf(m0, pm0), mn1 = fmaxf(m1, pm1);
        const float c0 = exp2_f32(m0 - mn0), c1 = exp2_f32(m1 - mn1);
        float ls0 = 0.f, ls1 = 0.f;
#pragma unroll
        for (int nt = 0; nt < 8; ++nt) {
            const uint32_t p01 = exp2_f16x2(accS[nt][0] - mn0, accS[nt][1] - mn0);
            const uint32_t p23 = exp2_f16x2(accS[nt][2] - mn1, accS[nt][3] - mn1);
            *(uint32_t*)(Ps + (row0)     * AP + nt * 8 + 2 * t) = p01;
            *(uint32_t*)(Ps + (row0 + 8) * AP + nt * 8 + 2 * t) = p23;
            const float2 f01 = __half22float2(*(const __half2*)&p01);
            const float2 f23 = __half22float2(*(const __half2*)&p23);
            ls0 += f01.x + f01.y;
            ls1 += f23.x + f23.y;
        }
        ls0 += __shfl_xor_sync(0xffffffffu, ls0, 1);
        ls0 += __shfl_xor_sync(0xffffffffu, ls0, 2);
        ls1 += __shfl_xor_sync(0xffffffffu, ls1, 1);
        ls1 += __shfl_xor_sync(0xffffffffu, ls1, 2);
        l0 = l0 * c0 + ls0;
        l1 = l1 * c1 + ls1;
        m0 = mn0; m1 = mn1;
#pragma unroll
        for (int nt = 0; nt < 8; ++nt) {
            accO[nt][0] *= c0; accO[nt][1] *= c0;
            accO[nt][2] *= c1; accO[nt][3] *= c1;
        }
        __syncwarp();

#pragma unroll
        for (int kc = 0; kc < 4; ++kc) {
            const int koff = kc * 16;
            uint32_t a[4];
            a[0] = ldu32(Ps + (row0)     * AP + koff + 2 * t);
            a[1] = ldu32(Ps + (row0 + 8) * AP + koff + 2 * t);
            a[2] = ldu32(Ps + (row0)     * AP + koff + 2 * t + 8);
            a[3] = ldu32(Ps + (row0 + 8) * AP + koff + 2 * t + 8);
#pragma unroll
            for (int ntp = 0; ntp < 4; ++ntp) {
                uint32_t b0, b1, b2, b3;
                ldsm_x4_trans(b0, b1, b2, b3,
                              vbase + (uint32_t)((koff * AP + ntp * 16) * 2));
                uint32_t bf0[2] = { b0, b1 };
                uint32_t bf1[2] = { b2, b3 };
                mma_f16(accO[2 * ntp],     a, bf0);
                mma_f16(accO[2 * ntp + 1], a, bf1);
            }
        }

        if (it + 1 < niter) {
            __syncthreads();
            load_kv(k0 + 64);
            CP_COMMIT(); CP_WAIT0();
            __syncthreads();
        }
    }

    const float rl0 = 1.0f / l0, rl1 = 1.0f / l1;
    __half* o0 = out + (size_t)(b * SEQ + qrow0) * DMODEL + h * DH;
    __half* o1 = out + (size_t)(b * SEQ + qrow1) * DMODEL + h * DH;
#pragma unroll
    for (int nt = 0; nt < 8; ++nt) {
        const int col = nt * 8 + 2 * t;
        *(__half2*)(o0 + col) = __floats2half2_rn(accO[nt][0] * rl0, accO[nt][1] * rl0);
        *(__half2*)(o1 + col) = __floats2half2_rn(accO[nt][2] * rl1, accO[nt][3] * rl1);
    }
}

// ---------------------------------------------------------------------------
// kernel_launch
// ---------------------------------------------------------------------------
extern "C" void kernel_launch(void* const* d_in, const int* in_sizes, int n_in,
                              void* d_out, int out_size)
{
    const float* x     = (const float*)d_in[0];
    const float* W_qkv = (const float*)d_in[1];
    const float* b_qkv = (const float*)d_in[2];
    const float* W_out = (const float*)d_in[3];
    const float* b_out = (const float*)d_in[4];
    float* out = (float*)d_out;

    __half* qkv; cudaGetSymbolAddress((void**)&qkv, g_qkv);
    __half* att; cudaGetSymbolAddress((void**)&att, g_att);
    __half* xh;  cudaGetSymbolAddress((void**)&xh,  g_xh);
    __half* wtq; cudaGetSymbolAddress((void**)&wtq, g_wtq);
    __half* wto; cudaGetSymbolAddress((void**)&wto, g_wto);

    cudaFuncSetAttribute(gemm_f16_512<1>,
                         cudaFuncAttributeMaxDynamicSharedMemorySize, GSMEM_BYTES);
    cudaFuncSetAttribute(gemm_f16_512<0>,
                         cudaFuncAttributeMaxDynamicSharedMemorySize, GSMEM_BYTES);
    cudaFuncSetAttribute(attn_f16_kernel,
                         cudaFuncAttributeMaxDynamicSharedMemorySize, ATT_SMEM_BYTES);

    // 0) merged precondition (x->f16, W_qkv^T, W_out^T) — one launch
    precond_kernel<<<NB_TOT, dim3(32, 8)>>>(x, xh, W_qkv, wtq, W_out, wto);

    // 1) QKV projection (16-warp fp16 GEMM), output fp16
    {
        dim3 grid(QKV_N / GBN, MTOT / GBM);   // (12, 64) = 768 CTAs
        gemm_f16_512<1><<<grid, 512, GSMEM_BYTES>>>(xh, wtq, b_qkv, qkv, QKV_N);
    }
    // 2) Causal attention
    {
        dim3 grid(SEQ / 128, BATCH * NHEAD);  // (16, 64)
        attn_f16_kernel<<<grid, 256, ATT_SMEM_BYTES>>>(qkv, att);
    }
    // 3) Output projection, fp32 out
    {
        dim3 grid(DMODEL / GBN, MTOT / GBM);  // (4, 64) = 256 CTAs
        gemm_f16_512<0><<<grid, 512, GSMEM_BYTES>>>(att, wto, b_out, out, DMODEL);
    }
}

// round 17
// speedup vs baseline: 2.0579x; 1.0145x over previous
#include <cuda_runtime.h>
#include <cuda_fp16.h>
#include <math.h>
#include <stdint.h>

// Problem constants
#define BATCH   4
#define SEQ     2048
#define DMODEL  1024
#define NHEAD   16
#define DH      64
#define MTOT    (BATCH * SEQ)       // 8192
#define QKV_N   (3 * DMODEL)        // 3072
#define KDIM    DMODEL

// ---------------------------------------------------------------------------
// Scratch (device globals: allocation-free rule)
// ---------------------------------------------------------------------------
__device__ __half g_qkv[(size_t)MTOT * QKV_N];     // [8192,3072] fp16
__device__ __half g_att[(size_t)MTOT * DMODEL];    // [8192,1024] fp16
__device__ __half g_xh[(size_t)MTOT * DMODEL];     // x -> fp16
__device__ __half g_wtq[(size_t)QKV_N * DMODEL];   // W_qkv^T fp16
__device__ __half g_wto[(size_t)DMODEL * DMODEL];  // W_out^T fp16

// ---------------------------------------------------------------------------
// Helpers (portable sm_80+ PTX only)
// ---------------------------------------------------------------------------
__device__ __forceinline__ uint32_t smem_u32(const void* p) {
    uint32_t a;
    asm("{ .reg .u64 t; cvta.to.shared.u64 t, %1; cvt.u32.u64 %0, t; }" : "=r"(a) : "l"(p));
    return a;
}
__device__ __forceinline__ void cp16(uint32_t dst, const void* src) {
    asm volatile("cp.async.cg.shared.global [%0], [%1], 16;" :: "r"(dst), "l"(src));
}
#define CP_COMMIT()  asm volatile("cp.async.commit_group;" ::: "memory")
#define CP_WAIT1()   asm volatile("cp.async.wait_group 1;" ::: "memory")
#define CP_WAIT0()   asm volatile("cp.async.wait_group 0;" ::: "memory")

__device__ __forceinline__ void mma_f16(float* d, const uint32_t* a, const uint32_t* b) {
    asm volatile(
        "mma.sync.aligned.m16n8k16.row.col.f32.f16.f16.f32 "
        "{%0,%1,%2,%3}, {%4,%5,%6,%7}, {%8,%9}, {%0,%1,%2,%3};"
        : "+f"(d[0]), "+f"(d[1]), "+f"(d[2]), "+f"(d[3])
        : "r"(a[0]), "r"(a[1]), "r"(a[2]), "r"(a[3]), "r"(b[0]), "r"(b[1]));
}
__device__ __forceinline__ uint32_t ldu32(const __half* p) {
    return *(const uint32_t*)p;
}
__device__ __forceinline__ void ldsm_x4(uint32_t& r0, uint32_t& r1,
                                        uint32_t& r2, uint32_t& r3, uint32_t addr) {
    asm volatile("ldmatrix.sync.aligned.m8n8.x4.shared.b16 {%0,%1,%2,%3}, [%4];"
                 : "=r"(r0), "=r"(r1), "=r"(r2), "=r"(r3) : "r"(addr));
}
__device__ __forceinline__ void ldsm_x4_trans(uint32_t& r0, uint32_t& r1,
                                              uint32_t& r2, uint32_t& r3, uint32_t addr) {
    asm volatile("ldmatrix.sync.aligned.m8n8.x4.trans.shared.b16 {%0,%1,%2,%3}, [%4];"
                 : "=r"(r0), "=r"(r1), "=r"(r2), "=r"(r3) : "r"(addr));
}
__device__ __forceinline__ uint32_t exp2_f16x2(float lo, float hi) {
    uint32_t h, p;
    asm("cvt.rn.f16x2.f32 %0, %1, %2;" : "=r"(h) : "f"(hi), "f"(lo));
    asm("ex2.approx.f16x2 %0, %1;" : "=r"(p) : "r"(h));
    return p;
}
__device__ __forceinline__ float exp2_f32(float x) {
    float r;
    asm("ex2.approx.f32 %0, %1;" : "=f"(r) : "f"(x));
    return r;
}

// Per-lane ldmatrix relative offsets (in halves), pitch P (halves)
__device__ __forceinline__ uint32_t arel_of(int lane, int P) {
    return (uint32_t)((((lane >> 3) & 1) * 8 + (lane & 7)) * P + ((lane >> 4) & 1) * 8);
}
__device__ __forceinline__ uint32_t brel_of(int lane, int P) {
    return (uint32_t)((((lane >> 4) & 1) * 8 + (lane & 7)) * P + ((lane >> 3) & 1) * 8);
}

// ---------------------------------------------------------------------------
// Unified fp16 GEMM (round-12, AT the mma.sync throughput floor — unchanged):
// 512 threads = 16 warps (4m x 4n), CTA tile 128x256, warp tile 32x64, BK=64.
// ---------------------------------------------------------------------------
#define PH 72
#define GBM 128
#define GBN 256
#define GA_HALVES (GBM * PH)
#define GB_HALVES (GBN * PH)
#define GSTAGE    (GA_HALVES + GB_HALVES)
#define GSMEM_BYTES (3 * GSTAGE * 2)
#define NCHUNK (KDIM / 64)

template <int OUT_HALF>
__global__ __launch_bounds__(512, 1)
void gemm_f16_512(const __half* __restrict__ A, const __half* __restrict__ Bt,
                  const float* __restrict__ bias, void* __restrict__ Cv, int Ntot)
{
    extern __shared__ __align__(16) __half smh[];

    const int tid = threadIdx.x;
    const int wid = tid >> 5;
    const int lane = tid & 31;
    const int g = lane >> 2;
    const int t = lane & 3;
    const int wm = wid >> 2;
    const int wn = wid & 3;

    const int m0 = blockIdx.y * GBM;
    const int n0 = blockIdx.x * GBN;

    const __half* Abase = A  + (size_t)m0 * KDIM;
    const __half* Bbase = Bt + (size_t)n0 * KDIM;
    const uint32_t smu = smem_u32(smh);

    const uint32_t awoff = (uint32_t)(wm * 32 * PH) * 2u + arel_of(lane, PH) * 2u;
    const uint32_t bwoff = (uint32_t)(GA_HALVES + wn * 64 * PH) * 2u + brel_of(lane, PH) * 2u;

    auto load_chunk = [&](int c, int st) {
        const int k0 = c * 64;
        const uint32_t sa = smu + (uint32_t)(st * GSTAGE) * 2u;
        const uint32_t sb = sa + (uint32_t)GA_HALVES * 2u;
#pragma unroll
        for (int i = 0; i < 2; ++i) {
            const int e = tid + 512 * i;
            const int r = e >> 3, q = e & 7;
            cp16(sa + (uint32_t)(r * PH + q * 8) * 2u, Abase + (size_t)r * KDIM + k0 + q * 8);
        }
#pragma unroll
        for (int i = 0; i < 4; ++i) {
            const int e = tid + 512 * i;
            const int r = e >> 3, q = e & 7;
            cp16(sb + (uint32_t)(r * PH + q * 8) * 2u, Bbase + (size_t)r * KDIM + k0 + q * 8);
        }
        CP_COMMIT();
    };

    float acc[2][8][4];
#pragma unroll
    for (int i = 0; i < 2; ++i)
#pragma unroll
        for (int j = 0; j < 8; ++j)
#pragma unroll
            for (int r = 0; r < 4; ++r) acc[i][j][r] = 0.f;

    load_chunk(0, 0);
    load_chunk(1, 1);

    for (int c = 0; c < NCHUNK; ++c) {
        const int s = c % 3;
        if (c + 1 < NCHUNK) CP_WAIT1(); else CP_WAIT0();
        __syncthreads();

        const uint32_t stg = smu + (uint32_t)(s * GSTAGE) * 2u;
        const uint32_t aB = stg + awoff;
        const uint32_t bB = stg + bwoff;

#pragma unroll
        for (int ks = 0; ks < 4; ++ks) {
            const uint32_t ko = (uint32_t)(ks * 16) * 2u;
            uint32_t af[2][4], bf[8][2];
#pragma unroll
            for (int mt = 0; mt < 2; ++mt)
                ldsm_x4(af[mt][0], af[mt][1], af[mt][2], af[mt][3],
                        aB + (uint32_t)(mt * 16 * PH) * 2u + ko);
#pragma unroll
            for (int np = 0; np < 4; ++np)
                ldsm_x4(bf[2 * np][0], bf[2 * np][1], bf[2 * np + 1][0], bf[2 * np + 1][1],
                        bB + (uint32_t)(np * 16 * PH) * 2u + ko);
#pragma unroll
            for (int mt = 0; mt < 2; ++mt)
#pragma unroll
                for (int nt = 0; nt < 8; ++nt)
                    mma_f16(acc[mt][nt], af[mt], bf[nt]);
        }

        if (c + 2 < NCHUNK) load_chunk(c + 2, (c + 2) % 3);
    }

#pragma unroll
    for (int mt = 0; mt < 2; ++mt) {
        const int row = m0 + wm * 32 + mt * 16 + g;
#pragma unroll
        for (int nt = 0; nt < 8; ++nt) {
            const int col = n0 + wn * 64 + nt * 8 + t * 2;
            const float bx = __ldg(bias + col), by = __ldg(bias + col + 1);
            if (OUT_HALF) {
                __half* C = (__half*)Cv;
                *(__half2*)(C + (size_t)row * Ntot + col) =
                    __floats2half2_rn(acc[mt][nt][0] + bx, acc[mt][nt][1] + by);
                *(__half2*)(C + (size_t)(row + 8) * Ntot + col) =
                    __floats2half2_rn(acc[mt][nt][2] + bx, acc[mt][nt][3] + by);
            } else {
                float* C = (float*)Cv;
                float2 lo = { acc[mt][nt][0] + bx, acc[mt][nt][1] + by };
                float2 hi = { acc[mt][nt][2] + bx, acc[mt][nt][3] + by };
                *(float2*)(C + (size_t)row * Ntot + col)       = lo;
                *(float2*)(C + (size_t)(row + 8) * Ntot + col) = hi;
            }
        }
    }
}

// ---------------------------------------------------------------------------
// Merged preconditioning (round-12, fixed coverage — unchanged).
// ---------------------------------------------------------------------------
#define NB_X   1024
#define NB_WQ  (96 * 32)
#define NB_WO  (32 * 32)
#define NB_TOT (NB_X + NB_WQ + NB_WO)

__global__ __launch_bounds__(256)
void precond_kernel(const float* __restrict__ x, __half* __restrict__ xh,
                    const float* __restrict__ Wq, __half* __restrict__ Wtq,
                    const float* __restrict__ Wo, __half* __restrict__ Wto)
{
    __shared__ float tbuf[32][33];
    const int bid = blockIdx.x;
    const int tx = threadIdx.x, ty = threadIdx.y;
    const int tid = ty * 32 + tx;

    if (bid < NB_X) {
        const int base = bid * 2048 + tid;
#pragma unroll
        for (int i = 0; i < 8; ++i) {
            const int idx = base + 256 * i;
            float4 v = ((const float4*)x)[idx];
            __half2 lo = __floats2half2_rn(v.x, v.y);
            __half2 hi = __floats2half2_rn(v.z, v.w);
            uint2 o = { *(uint32_t*)&lo, *(uint32_t*)&hi };
            ((uint2*)xh)[idx] = o;
        }
        return;
    }

    const float* W; __half* Wt; int N, tb;
    if (bid < NB_X + NB_WQ) { W = Wq; Wt = Wtq; N = QKV_N; tb = bid - NB_X; }
    else                    { W = Wo; Wt = Wto; N = DMODEL; tb = bid - NB_X - NB_WQ; }

    const int ntiles = N / 32;
    const int nb = (tb % ntiles) * 32;
    const int kb = (tb / ntiles) * 32;
#pragma unroll
    for (int i = 0; i < 32; i += 8)
        tbuf[ty + i][tx] = W[(size_t)(kb + ty + i) * N + nb + tx];
    __syncthreads();
#pragma unroll
    for (int i = 0; i < 32; i += 8)
        Wt[(size_t)(nb + ty + i) * KDIM + kb + tx] = __float2half_rn(tbuf[tx][ty + i]);
}

// ---------------------------------------------------------------------------
// fp16 causal flash attention with DOUBLE-BUFFERED 64-key K/V tiles.
// Smem (halves): Q[128][72] | K0 | V0 | K1 | V1 (64x72 each) | P[128][72]
//   = 36864 halves = 73728 B -> still 2 CTAs/SM.
// ---------------------------------------------------------------------------
#define AP 72
#define OFF_K  9216                       // K0; K1 = OFF_K + st*9216? see below
#define OFF_V  13824                      // V0
#define KVSTRIDE 9216                     // (K1-K0) = (V1-V0) = 64*72*2 halves
#define OFF_P  27648
#define ATT_SMEM_HALVES 36864
#define ATT_SMEM_BYTES  (ATT_SMEM_HALVES * 2)

__global__ __launch_bounds__(256, 2)
void attn_f16_kernel(const __half* __restrict__ qkv, __half* __restrict__ out)
{
    extern __shared__ __align__(16) __half smh[];
    const uint32_t smu = smem_u32(smh);

    const int tid = threadIdx.x;
    const int wid = tid >> 5;
    const int lane = tid & 31;
    const int g = lane >> 2, t = lane & 3;

    const int qt = gridDim.x - 1 - blockIdx.x;   // heavy tiles first
    const int q0 = qt * 128;
    const int bh = blockIdx.y;
    const int b = bh >> 4, h = bh & 15;

    const __half* base = qkv + (size_t)b * SEQ * QKV_N;

    // KV loader into buffer st (0/1): K at OFF_K + st*KVSTRIDE, V likewise
    auto load_kv = [&](int it, int st) {
        const int k0 = it * 64;
        const uint32_t kb = smu + (uint32_t)(OFF_K + st * KVSTRIDE) * 2u;
        const uint32_t vb = smu + (uint32_t)(OFF_V + st * KVSTRIDE) * 2u;
#pragma unroll
        for (int i = 0; i < 2; ++i) {
            const int e = tid + 256 * i;       // 0..511
            const int r = e >> 3, q = e & 7;
            const __half* krow = base + (size_t)(k0 + r) * QKV_N + DMODEL + h * DH + q * 8;
            const __half* vrow = base + (size_t)(k0 + r) * QKV_N + 2 * DMODEL + h * DH + q * 8;
            cp16(kb + (uint32_t)(r * AP + q * 8) * 2u, krow);
            cp16(vb + (uint32_t)(r * AP + q * 8) * 2u, vrow);
        }
        CP_COMMIT();
    };

    // stage Q together with KV tile 0 (same commit group)
#pragma unroll
    for (int i = 0; i < 4; ++i) {
        const int e = tid + 256 * i;
        const int r = e >> 3, q = e & 7;
        cp16(smu + (uint32_t)(r * AP + q * 8) * 2u,
             base + (size_t)(q0 + r) * QKV_N + h * DH + q * 8);
    }
    const int niter = 2 * (qt + 1);               // >= 2
    load_kv(0, 0);
    load_kv(1, 1);

    const int row0 = wid * 16 + g;
    const int qrow0 = q0 + row0;
    const int qrow1 = qrow0 + 8;
    const float l2s = 0.1803368801111204f;   // (1/8) * log2(e)

    const uint32_t qbase = smu + (uint32_t)(wid * 16 * AP) * 2u + arel_of(lane, AP) * 2u;
    const uint32_t kbase0 = smu + (uint32_t)(OFF_K) * 2u + brel_of(lane, AP) * 2u;
    const uint32_t vbase0 = smu +
        (uint32_t)((OFF_V + (lane & 15) * AP + ((lane >> 4) << 3)) * 2);

    float m0 = -INFINITY, m1 = -INFINITY, l0 = 0.f, l1 = 0.f;
    float accO[8][4];
#pragma unroll
    for (int nt = 0; nt < 8; ++nt)
#pragma unroll
        for (int r = 0; r < 4; ++r) accO[nt][r] = 0.f;

    __half* Ps = smh + OFF_P;
    uint32_t qf[4][4];
    bool qf_loaded = false;

    for (int it = 0; it < niter; ++it) {
        const int st = it & 1;
        const int k0 = it * 64;
        const uint32_t kvoff = (uint32_t)(st * KVSTRIDE) * 2u;

        if (it + 1 < niter) CP_WAIT1(); else CP_WAIT0();
        __syncthreads();                      // tile `it` (and Q on it==0) visible

        if (!qf_loaded) {                     // hoist Q fragments once (after Q landed)
#pragma unroll
            for (int kd = 0; kd < 4; ++kd)
                ldsm_x4(qf[kd][0], qf[kd][1], qf[kd][2], qf[kd][3],
                        qbase + (uint32_t)(kd * 16) * 2u);
            qf_loaded = true;
        }

        // ---- S = Q K^T ----
        float accS[8][4];
#pragma unroll
        for (int nt = 0; nt < 8; ++nt)
#pragma unroll
            for (int r = 0; r < 4; ++r) accS[nt][r] = 0.f;

#pragma unroll
        for (int kd = 0; kd < 4; ++kd) {
            const uint32_t ko = (uint32_t)(kd * 16) * 2u;
#pragma unroll
            for (int np = 0; np < 4; ++np) {
                uint32_t b0, b1, b2, b3;
                ldsm_x4(b0, b1, b2, b3,
                        kbase0 + kvoff + (uint32_t)(np * 16 * AP) * 2u + ko);
                uint32_t bf0[2] = { b0, b1 };
                uint32_t bf1[2] = { b2, b3 };
                mma_f16(accS[2 * np],     qf[kd], bf0);
                mma_f16(accS[2 * np + 1], qf[kd], bf1);
            }
        }

        // ---- mask + online softmax (log2 domain) ----
        float pm0 = -INFINITY, pm1 = -INFINITY;
#pragma unroll
        for (int nt = 0; nt < 8; ++nt) {
            const int key = k0 + nt * 8 + 2 * t;
            accS[nt][0] = (key     <= qrow0) ? accS[nt][0] * l2s : -INFINITY;
            accS[nt][1] = (key + 1 <= qrow0) ? accS[nt][1] * l2s : -INFINITY;
            accS[nt][2] = (key     <= qrow1) ? accS[nt][2] * l2s : -INFINITY;
            accS[nt][3] = (key + 1 <= qrow1) ? accS[nt][3] * l2s : -INFINITY;
            pm0 = fmaxf(pm0, fmaxf(accS[nt][0], accS[nt][1]));
            pm1 = fmaxf(pm1, fmaxf(accS[nt][2], accS[nt][3]));
        }
        pm0 = fmaxf(pm0, __shfl_xor_sync(0xffffffffu, pm0, 1));
        pm0 = fmaxf(pm0, __shfl_xor_sync(0xffffffffu, pm0, 2));
        pm1 = fmaxf(pm1, __shfl_xor_sync(0xffffffffu, pm1, 1));
        pm1 = fmaxf(pm1, __shfl_xor_sync(0xffffffffu, pm1, 2));

        const float mn0 = fmaxf(m0, pm0), mn1 = fmaxf(m1, pm1);
        const float c0 = exp2_f32(m0 - mn0), c1 = exp2_f32(m1 - mn1);
        float ls0 = 0.f, ls1 = 0.f;
#pragma unroll
        for (int nt = 0; nt < 8; ++nt) {
            const uint32_t p01 = exp2_f16x2(accS[nt][0] - mn0, accS[nt][1] - mn0);
            const uint32_t p23 = exp2_f16x2(accS[nt][2] - mn1, accS[nt][3] - mn1);
            *(uint32_t*)(Ps + (row0)     * AP + nt * 8 + 2 * t) = p01;
            *(uint32_t*)(Ps + (row0 + 8) * AP + nt * 8 + 2 * t) = p23;
            const float2 f01 = __half22float2(*(const __half2*)&p01);
            const float2 f23 = __half22float2(*(const __half2*)&p23);
            ls0 += f01.x + f01.y;
            ls1 += f23.x + f23.y;
        }
        ls0 += __shfl_xor_sync(0xffffffffu, ls0, 1);
        ls0 += __shfl_xor_sync(0xffffffffu, ls0, 2);
        ls1 += __shfl_xor_sync(0xffffffffu, ls1, 1);
        ls1 += __shfl_xor_sync(0xffffffffu, ls1, 2);
        l0 = l0 * c0 + ls0;
        l1 = l1 * c1 + ls1;
        m0 = mn0; m1 = mn1;
#pragma unroll
        for (int nt = 0; nt < 8; ++nt) {
            accO[nt][0] *= c0; accO[nt][1] *= c0;
            accO[nt][2] *= c1; accO[nt][3] *= c1;
        }
        __syncwarp();   // P tile is warp-private

        // ---- O += P V ----
#pragma unroll
        for (int kc = 0; kc < 4; ++kc) {
            const int koff = kc * 16;
            uint32_t a[4];
            a[0] = ldu32(Ps + (row0)     * AP + koff + 2 * t);
            a[1] = ldu32(Ps + (row0 + 8) * AP + koff + 2 * t);
            a[2] = ldu32(Ps + (row0)     * AP + koff + 2 * t + 8);
            a[3] = ldu32(Ps + (row0 + 8) * AP + koff + 2 * t + 8);
#pragma unroll
            for (int ntp = 0; ntp < 4; ++ntp) {
                uint32_t b0, b1, b2, b3;
                ldsm_x4_trans(b0, b1, b2, b3,
                              vbase0 + kvoff + (uint32_t)((koff * AP + ntp * 16) * 2));
                uint32_t bf0[2] = { b0, b1 };
                uint32_t bf1[2] = { b2, b3 };
                mma_f16(accO[2 * ntp],     a, bf0);
                mma_f16(accO[2 * ntp + 1], a, bf1);
            }
        }

        __syncthreads();                       // all warps done reading buffer st
        if (it + 2 < niter) load_kv(it + 2, st);   // prefetch into freed buffer
    }

    // ---- normalize + write fp16 ----
    const float rl0 = 1.0f / l0, rl1 = 1.0f / l1;
    __half* o0 = out + (size_t)(b * SEQ + qrow0) * DMODEL + h * DH;
    __half* o1 = out + (size_t)(b * SEQ + qrow1) * DMODEL + h * DH;
#pragma unroll
    for (int nt = 0; nt < 8; ++nt) {
        const int col = nt * 8 + 2 * t;
        *(__half2*)(o0 + col) = __floats2half2_rn(accO[nt][0] * rl0, accO[nt][1] * rl0);
        *(__half2*)(o1 + col) = __floats2half2_rn(accO[nt][2] * rl1, accO[nt][3] * rl1);
    }
}

// ---------------------------------------------------------------------------
// kernel_launch
// ---------------------------------------------------------------------------
extern "C" void kernel_launch(void* const* d_in, const int* in_sizes, int n_in,
                              void* d_out, int out_size)
{
    const float* x     = (const float*)d_in[0];
    const float* W_qkv = (const float*)d_in[1];
    const float* b_qkv = (const float*)d_in[2];
    const float* W_out = (const float*)d_in[3];
    const float* b_out = (const float*)d_in[4];
    float* out = (float*)d_out;

    __half* qkv; cudaGetSymbolAddress((void**)&qkv, g_qkv);
    __half* att; cudaGetSymbolAddress((void**)&att, g_att);
    __half* xh;  cudaGetSymbolAddress((void**)&xh,  g_xh);
    __half* wtq; cudaGetSymbolAddress((void**)&wtq, g_wtq);
    __half* wto; cudaGetSymbolAddress((void**)&wto, g_wto);

    cudaFuncSetAttribute(gemm_f16_512<1>,
                         cudaFuncAttributeMaxDynamicSharedMemorySize, GSMEM_BYTES);
    cudaFuncSetAttribute(gemm_f16_512<0>,
                         cudaFuncAttributeMaxDynamicSharedMemorySize, GSMEM_BYTES);
    cudaFuncSetAttribute(attn_f16_kernel,
                         cudaFuncAttributeMaxDynamicSharedMemorySize, ATT_SMEM_BYTES);

    // 0) merged precondition (x->f16, W_qkv^T, W_out^T)
    precond_kernel<<<NB_TOT, dim3(32, 8)>>>(x, xh, W_qkv, wtq, W_out, wto);

    // 1) QKV projection
    {
        dim3 grid(QKV_N / GBN, MTOT / GBM);   // (12, 64)
        gemm_f16_512<1><<<grid, 512, GSMEM_BYTES>>>(xh, wtq, b_qkv, qkv, QKV_N);
    }
    // 2) Causal attention (double-buffered 64-key K/V)
    {
        dim3 grid(SEQ / 128, BATCH * NHEAD);  // (16, 64)
        attn_f16_kernel<<<grid, 256, ATT_SMEM_BYTES>>>(qkv, att);
    }
    // 3) Output projection
    {
        dim3 grid(DMODEL / GBN, MTOT / GBM);  // (4, 64)
        gemm_f16_512<0><<<grid, 512, GSMEM_BYTES>>>(att, wto, b_out, out, DMODEL);
    }
}